// round 12
// baseline (speedup 1.0000x reference)
#include <cuda_runtime.h>
#include <cuda_bf16.h>
#include <math.h>
#include <stdint.h>

// ---------------- problem constants ----------------
#define Pn 2
#define Bn 2
#define Sn 2048
#define Dn 1024
#define TOK 4096

// ---------------- scratch: packed bf16x2 split planes (uint2 = {hi-pair, lo-pair}) ----------------
__device__ __align__(16) uint2 g_Xs[(size_t)TOK*512];       // x, d-pair packed
__device__ __align__(16) uint2 g_Falls[(size_t)512*1024];   // f_neurons^T, d(k)-pair packed
__device__ __align__(16) uint2 g_Rs[(size_t)256*1024];      // r_neurons (qk|v), k-pair packed
__device__ __align__(16) uint2 g_WOs[(size_t)512*1024];     // W_O, k-pair packed
__device__ __align__(16) uint2 g_Cs[(size_t)3*TOK*128];     // CQ|CK|CV, k-pair packed
__device__ __align__(16) uint2 g_Qpk[(size_t)TOK*512];      // Q, d-pair packed
__device__ __align__(16) uint2 g_Kpk[(size_t)TOK*512];      // K, d-pair packed
__device__ __align__(16) uint2 g_Vpk[(size_t)(TOK/2)*1024]; // V, key-pair packed
__device__ __align__(16) uint2 g_AOs[(size_t)TOK*512];      // attn out, d-pair packed
__device__ __align__(16) float g_AH[(size_t)TOK*Dn];        // all_h (router input)
__device__ float g_qsq[TOK];                                // |Q|^2 partials
__device__ float g_rsum[48];

// ---------------- helpers ----------------
__device__ __forceinline__ uint32_t bf16bits(float x) {
    __nv_bfloat16 h = __float2bfloat16_rn(x);
    return (uint32_t)*reinterpret_cast<uint16_t*>(&h);
}
__device__ __forceinline__ float bf16val(uint32_t b) {
    uint16_t u = (uint16_t)b;
    __nv_bfloat16 h = *reinterpret_cast<__nv_bfloat16*>(&u);
    return __bfloat162float(h);
}
__device__ __forceinline__ uint2 bfsplit2(float a, float b) {
    uint32_t ha = bf16bits(a), hb = bf16bits(b);
    uint32_t la = bf16bits(a - bf16val(ha));
    uint32_t lb = bf16bits(b - bf16val(hb));
    return make_uint2(ha | (hb << 16), la | (lb << 16));
}
__device__ __forceinline__ void mma_bf16(float* d, const uint32_t* a, uint32_t b0, uint32_t b1) {
    asm volatile("mma.sync.aligned.m16n8k16.row.col.f32.bf16.bf16.f32 "
                 "{%0,%1,%2,%3},{%4,%5,%6,%7},{%8,%9},{%0,%1,%2,%3};"
                 : "+f"(d[0]), "+f"(d[1]), "+f"(d[2]), "+f"(d[3])
                 : "r"(a[0]), "r"(a[1]), "r"(a[2]), "r"(a[3]), "r"(b0), "r"(b1));
}
__device__ __forceinline__ void cpa16(void* smem, const void* gmem) {
    uint32_t s = (uint32_t)__cvta_generic_to_shared(smem);
    asm volatile("cp.async.cg.shared.global [%0], [%1], 16;" :: "r"(s), "l"(gmem) : "memory");
}
__device__ __forceinline__ void cpcommit() { asm volatile("cp.async.commit_group;" ::: "memory"); }
template<int N>
__device__ __forceinline__ void cpwaitN() { asm volatile("cp.async.wait_group %0;" :: "n"(N) : "memory"); }

// ---------------- prep: transpose+split f_neurons, zero accumulators ----------------
__global__ void k_prep(const float* __restrict__ fneu) {
    int idx = blockIdx.x * blockDim.x + threadIdx.x;
    if (blockIdx.x == 0 && threadIdx.x < 48) g_rsum[threadIdx.x] = 0.f;
    if (idx < TOK) g_qsq[idx] = 0.f;
    if (idx < 512 * 1024) {
        int d2 = idx >> 10, c = idx & 1023;
        int n = c >> 4, r = c & 15;
        float v0 = fneu[((size_t)n * 1024 + 2 * d2) * 16 + r];
        float v1 = fneu[((size_t)n * 1024 + 2 * d2 + 1) * 16 + r];
        g_Falls[idx] = bfsplit2(v0, v1);
    }
}

// ---------------- split kernels ----------------
template<int W>
__global__ void k_split(const float* __restrict__ src, int n) {
    int idx = blockIdx.x * blockDim.x + threadIdx.x;
    if (idx >= n) return;
    if (W == 0) {
        float2 v = *reinterpret_cast<const float2*>(src + (size_t)2 * idx);
        g_Xs[idx] = bfsplit2(v.x, v.y);
    }
    if (W == 1) {
        int k2 = idx >> 10, c = idx & 1023;
        g_Rs[idx] = bfsplit2(src[(size_t)2 * k2 * 1024 + c], src[(size_t)(2 * k2 + 1) * 1024 + c]);
    }
    if (W == 2) {
        int k2 = idx >> 10, c = idx & 1023;
        g_WOs[idx] = bfsplit2(src[(size_t)2 * k2 * 1024 + c], src[(size_t)(2 * k2 + 1) * 1024 + c]);
    }
}

// ---------------- 3xbf16 GEMM, 3-stage cp.async pipeline ----------------
// block tile 128x128x16, 8 warps (4x2). Operands pre-split bf16-packed (uint2).
// MODE 0: AH = X @ Fall.   MODE 12: QKV = C @ r (grid y=96; by<64 -> Q,K; else V).
// MODE 3: out = AO @ W_O.
#define AS2 12    /* As row stride in uint2 */
#define BS2 132   /* Bs row stride in uint2 */
#define GEMM_SMEM ((3*128*AS2 + 3*8*BS2) * 8)
template<int MODE>
__global__ __launch_bounds__(256) void k_mma(float* __restrict__ extC) {
    constexpr int K2 = (MODE == 12) ? 128 : 512;   // k-pairs per row
    constexpr int N = 1024;
    constexpr int NIT = K2 / 8;

    const uint2* A; const uint2* B;
    if (MODE == 0)  { A = g_Xs;  B = g_Falls; }
    if (MODE == 12) { A = g_Cs;  B = (blockIdx.y < 64) ? g_Rs : (g_Rs + (size_t)128 * 1024); }
    if (MODE == 3)  { A = g_AOs; B = g_WOs; }

    extern __shared__ uint2 sm[];
    uint2* As = sm;                    // [3][128][AS2]
    uint2* Bs = sm + 3 * 128 * AS2;    // [3][8][BS2]

    const int tid  = threadIdx.x;
    const int lane = tid & 31;
    const int warp = tid >> 5;
    const int wr = warp >> 1;
    const int wc = warp & 1;
    const int g = lane >> 2;
    const int t = lane & 3;
    const int bx = blockIdx.x, by = blockIdx.y;

    float acc[2][8][4];
    #pragma unroll
    for (int mi = 0; mi < 2; mi++)
        #pragma unroll
        for (int ni = 0; ni < 8; ni++)
            #pragma unroll
            for (int j = 0; j < 4; j++) acc[mi][ni][j] = 0.f;

    const uint2* Ab = A + (size_t)by * 128 * K2;
    const uint2* Bb = B + (size_t)bx * 128;

    auto loadStage = [&](int st, int k20) {
        #pragma unroll
        for (int i = 0; i < 2; i++) {
            int chunk = tid + i * 256;
            int r = chunk >> 2, cc = (chunk & 3) * 2;
            cpa16(&As[(st * 128 + r) * AS2 + cc], Ab + (size_t)r * K2 + k20 + cc);
        }
        #pragma unroll
        for (int i = 0; i < 2; i++) {
            int chunk = tid + i * 256;
            int kr = chunk >> 6, cc = (chunk & 63) * 2;
            cpa16(&Bs[(st * 8 + kr) * BS2 + cc], Bb + (size_t)(k20 + kr) * N + cc);
        }
    };

    loadStage(0, 0); cpcommit();
    loadStage(1, 8); cpcommit();

    for (int it = 0; it < NIT; it++) {
        if (it + 1 < NIT) cpwaitN<1>(); else cpwaitN<0>();
        __syncthreads();
        if (it + 2 < NIT) { loadStage((it + 2) % 3, (it + 2) * 8); cpcommit(); }

        const int st = it % 3;
        uint32_t ah[2][4], al[2][4];
        #pragma unroll
        for (int mi = 0; mi < 2; mi++) {
            int r0 = wr * 32 + mi * 16 + g;
            uint2 a0 = As[(st * 128 + r0) * AS2 + t];
            uint2 a1 = As[(st * 128 + r0 + 8) * AS2 + t];
            uint2 a2 = As[(st * 128 + r0) * AS2 + t + 4];
            uint2 a3 = As[(st * 128 + r0 + 8) * AS2 + t + 4];
            ah[mi][0] = a0.x; ah[mi][1] = a1.x; ah[mi][2] = a2.x; ah[mi][3] = a3.x;
            al[mi][0] = a0.y; al[mi][1] = a1.y; al[mi][2] = a2.y; al[mi][3] = a3.y;
        }
        #pragma unroll
        for (int ni = 0; ni < 8; ni++) {
            int c = wc * 64 + ni * 8 + g;
            uint2 b0 = Bs[(st * 8 + t) * BS2 + c];
            uint2 b1 = Bs[(st * 8 + t + 4) * BS2 + c];
            #pragma unroll
            for (int mi = 0; mi < 2; mi++) {
                mma_bf16(acc[mi][ni], ah[mi], b0.x, b1.x);
                mma_bf16(acc[mi][ni], al[mi], b0.x, b1.x);
                mma_bf16(acc[mi][ni], ah[mi], b0.y, b1.y);
            }
        }
    }

    // epilogue
    #pragma unroll
    for (int mi = 0; mi < 2; mi++) {
        int r0 = by * 128 + wr * 32 + mi * 16 + g;
        float qs0 = 0.f, qs1 = 0.f;
        #pragma unroll
        for (int ni = 0; ni < 8; ni++) {
            int c = bx * 128 + wc * 64 + ni * 8 + 2 * t;
            int cp = c >> 1;
            float v0 = acc[mi][ni][0], v1 = acc[mi][ni][1];
            float v2 = acc[mi][ni][2], v3 = acc[mi][ni][3];
            if (MODE == 0) {
                *reinterpret_cast<float2*>(g_AH + (size_t)r0 * N + c) = make_float2(v0, v1);
                *reinterpret_cast<float2*>(g_AH + (size_t)(r0 + 8) * N + c) = make_float2(v2, v3);
            }
            if (MODE == 3) {
                *reinterpret_cast<float2*>(extC + (size_t)r0 * N + c) = make_float2(v0, v1);
                *reinterpret_cast<float2*>(extC + (size_t)(r0 + 8) * N + c) = make_float2(v2, v3);
            }
            if (MODE == 12) {
                if (r0 < TOK) {            // Q rows
                    qs0 += v0 * v0 + v1 * v1;
                    qs1 += v2 * v2 + v3 * v3;
                    g_Qpk[(size_t)r0 * 512 + cp] = bfsplit2(v0, v1);
                    g_Qpk[(size_t)(r0 + 8) * 512 + cp] = bfsplit2(v2, v3);
                } else if (r0 < 2 * TOK) { // K rows
                    g_Kpk[(size_t)(r0 - TOK) * 512 + cp] = bfsplit2(v0, v1);
                    g_Kpk[(size_t)(r0 + 8 - TOK) * 512 + cp] = bfsplit2(v2, v3);
                } else {                   // V rows: fused key-pair packing via shfl
                    float q0 = __shfl_xor_sync(0xffffffffu, v0, 4);
                    float q1 = __shfl_xor_sync(0xffffffffu, v1, 4);
                    float q2 = __shfl_xor_sync(0xffffffffu, v2, 4);
                    float q3 = __shfl_xor_sync(0xffffffffu, v3, 4);
                    int vtok = (r0 & ~1) - 2 * TOK;       // even token of the pair
                    int vb = vtok >> 11;
                    int klp = (vtok & 2047) >> 1;
                    int cc = c + (g & 1);                  // even g -> col c, odd g -> col c+1
                    size_t base = (size_t)(vb * 1024 + klp) * 1024 + cc;
                    if ((g & 1) == 0) {
                        g_Vpk[base] = bfsplit2(v0, q0);
                        g_Vpk[base + (size_t)4 * 1024] = bfsplit2(v2, q2);
                    } else {
                        g_Vpk[base] = bfsplit2(q1, v1);
                        g_Vpk[base + (size_t)4 * 1024] = bfsplit2(q3, v3);
                    }
                }
            }
        }
        if (MODE == 12 && r0 < TOK) {
            atomicAdd(&g_qsq[r0], qs0);
            atomicAdd(&g_qsq[r0 + 8], qs1);
        }
    }
}

// ---------------- per-token router / coefficient kernel ----------------
__global__ __launch_bounds__(128) void k_router(
    const float* __restrict__ wQg, const float* __restrict__ wKg, const float* __restrict__ wVg,
    const float* __restrict__ fqk_emb, const float* __restrict__ fv_emb,
    const float* __restrict__ Wp_qk, const float* __restrict__ bp_qk,
    const float* __restrict__ Wp_v, const float* __restrict__ bp_v,
    const float* __restrict__ Wr_qk, const float* __restrict__ Wr_v)
{
    const int t = blockIdx.x;
    const int tid = threadIdx.x;
    __shared__ float AHs[Dn];
    __shared__ float gate[3][32];
    __shared__ float hs[3][16];
    __shared__ float ins[3][128];
    __shared__ float lg[3][16];
    __shared__ float wsm[3][16];
    __shared__ float cbuf[768];

    for (int i = tid; i < Dn; i += 128) AHs[i] = g_AH[(size_t)t * Dn + i];

    float cacc[6] = {0.f, 0.f, 0.f, 0.f, 0.f, 0.f};
    float sumAcc = 0.f;

    for (int p = 0; p < Pn; p++) {
        __syncthreads();
        if (tid < 96) {
            int router = tid >> 5, n = tid & 31;
            const float* src = (router == 0) ? wQg : ((router == 1) ? wKg : wVg);
            gate[router][n] = src[((size_t)p * TOK + t) * 32 + n];
        }
        __syncthreads();
        if (tid < 48) {
            int router = tid >> 4, r = tid & 15;
            int base = (router == 2) ? 512 : 0;
            float a = 0.f;
            #pragma unroll
            for (int n = 0; n < 32; n++) a += gate[router][n] * AHs[base + n * 16 + r];
            hs[router][r] = a;
        }
        __syncthreads();
        for (int v = tid; v < 384; v += 128) {
            int router = v >> 7, i = v & 127;
            float val;
            if (i < 64) {
                const float* Wp = (router == 2) ? Wp_v : Wp_qk;
                const float* bp = (router == 2) ? bp_v : bp_qk;
                float a = bp[i];
                #pragma unroll
                for (int r = 0; r < 16; r++) a += hs[router][r] * Wp[r * 64 + i];
                val = a;
            } else {
                int d = i - 64;
                const float* emb = (router == 2) ? fv_emb : fqk_emb;
                float a = 0.f;
                #pragma unroll
                for (int n = 0; n < 32; n++) a += gate[router][n] * emb[n * 64 + d];
                val = a;
            }
            ins[router][i] = val;
        }
        __syncthreads();
        if (tid < 48) {
            int router = tid >> 4, j = tid & 15;
            const float* Wr = (router == 2) ? Wr_v : Wr_qk;
            float a = 0.f;
            for (int i = 0; i < 128; i++) a += ins[router][i] * Wr[i * 16 + j];
            lg[router][j] = a;
        }
        __syncthreads();
        if (tid < 3) {
            float mx = -1e30f;
            for (int j = 0; j < 16; j++) mx = fmaxf(mx, lg[tid][j]);
            float e[16], s = 0.f;
            for (int j = 0; j < 16; j++) { e[j] = __expf(lg[tid][j] - mx); s += e[j]; }
            float inv = 1.f / s;
            for (int j = 0; j < 16; j++) wsm[tid][j] = e[j] * inv;
        }
        __syncthreads();
        if (tid < 48) sumAcc += wsm[tid >> 4][tid & 15];
        #pragma unroll
        for (int it = 0; it < 6; it++) {
            int v = tid + it * 128;
            int router = v >> 8, idx = v & 255;
            cacc[it] += wsm[router][idx >> 4] * hs[router][idx & 15];
        }
    }
    #pragma unroll
    for (int it = 0; it < 6; it++) cbuf[tid + it * 128] = cacc[it];
    __syncthreads();
    for (int j = tid; j < 384; j += 128) {
        int router = j >> 7, j2 = j & 127;
        g_Cs[((size_t)router * TOK + t) * 128 + j2] =
            bfsplit2(cbuf[router * 256 + 2 * j2], cbuf[router * 256 + 2 * j2 + 1]);
    }
    if (tid < 48) atomicAdd(&g_rsum[tid], sumAcc);
}

// ---------------- 3xbf16 flash attention, 3-stage cp.async pipeline ----------------
// grid (S/128, B*H), 256 threads (8 warps), warp = 16 q rows, KV tile = 32.
// qt reversed so the longest (largest-qt) blocks launch first.
#define KS2 36   /* K row stride in uint2 */
#define VS2 68   /* V row stride in uint2 */
#define FLASH_SMEM ((3*32*KS2 + 3*16*VS2) * 8)
__global__ __launch_bounds__(256) void k_flashmma() {
    extern __shared__ uint2 fsm[];
    uint2* Ks = fsm;                   // [3][32][KS2]
    uint2* Vs = fsm + 3 * 32 * KS2;    // [3][16][VS2]

    const int qt = (int)(gridDim.x - 1 - blockIdx.x);
    const int bh = blockIdx.y;
    const int b = bh >> 4, h = bh & 15;
    const int tid = threadIdx.x;
    const int lane = tid & 31;
    const int warp = tid >> 5;
    const int g = lane >> 2, t = lane & 3;
    const int q0 = qt * 128 + warp * 16;

    uint32_t qh[4][4], ql[4][4];
    {
        const uint2* Qr0 = g_Qpk + (size_t)(b * Sn + q0 + g) * 512 + h * 32;
        const uint2* Qr1 = g_Qpk + (size_t)(b * Sn + q0 + g + 8) * 512 + h * 32;
        #pragma unroll
        for (int kc = 0; kc < 4; kc++) {
            uint2 a0 = Qr0[kc * 8 + t];
            uint2 a1 = Qr1[kc * 8 + t];
            uint2 a2 = Qr0[kc * 8 + t + 4];
            uint2 a3 = Qr1[kc * 8 + t + 4];
            qh[kc][0] = a0.x; qh[kc][1] = a1.x; qh[kc][2] = a2.x; qh[kc][3] = a3.x;
            ql[kc][0] = a0.y; ql[kc][1] = a1.y; ql[kc][2] = a2.y; ql[kc][3] = a3.y;
        }
    }

    float o[8][4];
    #pragma unroll
    for (int ni = 0; ni < 8; ni++)
        #pragma unroll
        for (int j = 0; j < 4; j++) o[ni][j] = 0.f;
    float m0 = -1e30f, m1 = -1e30f, l0 = 0.f, l1 = 0.f;

    const int nkt = 4 * qt + 4;

    auto loadKV = [&](int st, int kt) {
        #pragma unroll
        for (int i = 0; i < 4; i++) {
            int chunk = tid + i * 256;
            if (chunk < 512) {
                int r = chunk >> 4, cc = (chunk & 15) * 2;
                cpa16(&Ks[(st * 32 + r) * KS2 + cc],
                      g_Kpk + (size_t)(b * Sn + kt * 32 + r) * 512 + h * 32 + cc);
            } else {
                int c2 = chunk - 512;
                int r = c2 >> 5, cc = (c2 & 31) * 2;
                cpa16(&Vs[(st * 16 + r) * VS2 + cc],
                      g_Vpk + (size_t)(b * (Sn / 2) + kt * 16 + r) * 1024 + h * 64 + cc);
            }
        }
    };

    loadKV(0, 0); cpcommit();
    loadKV(1, 1); cpcommit();

    for (int kt = 0; kt < nkt; kt++) {
        if (kt + 1 < nkt) cpwaitN<1>(); else cpwaitN<0>();
        __syncthreads();
        if (kt + 2 < nkt) { loadKV((kt + 2) % 3, kt + 2); cpcommit(); }

        if (kt * 32 > q0 + 15) continue;   // fully masked for this warp
        const int st = kt % 3;

        float s[4][4];
        #pragma unroll
        for (int ni = 0; ni < 4; ni++)
            #pragma unroll
            for (int j = 0; j < 4; j++) s[ni][j] = 0.f;
        #pragma unroll
        for (int kc = 0; kc < 4; kc++) {
            #pragma unroll
            for (int ni = 0; ni < 4; ni++) {
                uint2 b0 = Ks[(st * 32 + ni * 8 + g) * KS2 + kc * 8 + t];
                uint2 b1 = Ks[(st * 32 + ni * 8 + g) * KS2 + kc * 8 + t + 4];
                mma_bf16(s[ni], qh[kc], b0.x, b1.x);
                mma_bf16(s[ni], ql[kc], b0.x, b1.x);
                mma_bf16(s[ni], qh[kc], b0.y, b1.y);
            }
        }
        #pragma unroll
        for (int ni = 0; ni < 4; ni++)
            #pragma unroll
            for (int j = 0; j < 4; j++) s[ni][j] *= 0.125f;

        if (kt * 32 + 31 > q0) {
            const int r0 = q0 + g, r1 = r0 + 8, cb = kt * 32;
            #pragma unroll
            for (int ni = 0; ni < 4; ni++) {
                int c0 = cb + ni * 8 + 2 * t;
                if (c0 > r0)     s[ni][0] = -1e30f;
                if (c0 + 1 > r0) s[ni][1] = -1e30f;
                if (c0 > r1)     s[ni][2] = -1e30f;
                if (c0 + 1 > r1) s[ni][3] = -1e30f;
            }
        }

        float mx0 = -1e30f, mx1 = -1e30f;
        #pragma unroll
        for (int ni = 0; ni < 4; ni++) {
            mx0 = fmaxf(mx0, fmaxf(s[ni][0], s[ni][1]));
            mx1 = fmaxf(mx1, fmaxf(s[ni][2], s[ni][3]));
        }
        mx0 = fmaxf(mx0, __shfl_xor_sync(0xffffffffu, mx0, 1));
        mx0 = fmaxf(mx0, __shfl_xor_sync(0xffffffffu, mx0, 2));
        mx1 = fmaxf(mx1, __shfl_xor_sync(0xffffffffu, mx1, 1));
        mx1 = fmaxf(mx1, __shfl_xor_sync(0xffffffffu, mx1, 2));
        float mn0 = fmaxf(m0, mx0), mn1 = fmaxf(m1, mx1);
        float cr0 = __expf(m0 - mn0), cr1 = __expf(m1 - mn1);
        m0 = mn0; m1 = mn1;
        #pragma unroll
        for (int ni = 0; ni < 8; ni++) {
            o[ni][0] *= cr0; o[ni][1] *= cr0;
            o[ni][2] *= cr1; o[ni][3] *= cr1;
        }

        float rs0 = 0.f, rs1 = 0.f;
        #pragma unroll
        for (int ni = 0; ni < 4; ni++) {
            s[ni][0] = __expf(s[ni][0] - m0);
            s[ni][1] = __expf(s[ni][1] - m0);
            s[ni][2] = __expf(s[ni][2] - m1);
            s[ni][3] = __expf(s[ni][3] - m1);
            rs0 += s[ni][0] + s[ni][1];
            rs1 += s[ni][2] + s[ni][3];
        }
        rs0 += __shfl_xor_sync(0xffffffffu, rs0, 1);
        rs0 += __shfl_xor_sync(0xffffffffu, rs0, 2);
        rs1 += __shfl_xor_sync(0xffffffffu, rs1, 1);
        rs1 += __shfl_xor_sync(0xffffffffu, rs1, 2);
        l0 = l0 * cr0 + rs0;
        l1 = l1 * cr1 + rs1;

        // P@V: C-fragment == A-fragment layout for bf16 — no shuffles
        #pragma unroll
        for (int kc = 0; kc < 2; kc++) {
            uint32_t pH[4], pL[4];
            uint2 f0 = bfsplit2(s[2 * kc][0], s[2 * kc][1]);
            uint2 f1 = bfsplit2(s[2 * kc][2], s[2 * kc][3]);
            uint2 f2 = bfsplit2(s[2 * kc + 1][0], s[2 * kc + 1][1]);
            uint2 f3 = bfsplit2(s[2 * kc + 1][2], s[2 * kc + 1][3]);
            pH[0] = f0.x; pH[1] = f1.x; pH[2] = f2.x; pH[3] = f3.x;
            pL[0] = f0.y; pL[1] = f1.y; pL[2] = f2.y; pL[3] = f3.y;
            #pragma unroll
            for (int ni = 0; ni < 8; ni++) {
                uint2 b0 = Vs[(st * 16 + kc * 8 + t) * VS2 + ni * 8 + g];
                uint2 b1 = Vs[(st * 16 + kc * 8 + t + 4) * VS2 + ni * 8 + g];
                mma_bf16(o[ni], pH, b0.x, b1.x);
                mma_bf16(o[ni], pL, b0.x, b1.x);
                mma_bf16(o[ni], pH, b0.y, b1.y);
            }
        }
    }

    // epilogue: normalize, q-norm scale, write packed AO
    const int r0 = q0 + g, r1 = r0 + 8;
    const int tb = b * Sn;
    float qsq0 = g_qsq[tb + r0], qsq1 = g_qsq[tb + r1];
    float sc0 = (qsq0 > 1e-12f) ? 1.f : sqrtf(qsq0) * 1e-6f;
    float sc1 = (qsq1 > 1e-12f) ? 1.f : sqrtf(qsq1) * 1e-6f;
    float f0 = sc0 / l0;
    float f1 = sc1 / l1;
    #pragma unroll
    for (int ni = 0; ni < 8; ni++) {
        int cp = h * 32 + ni * 4 + t;
        g_AOs[(size_t)(tb + r0) * 512 + cp] = bfsplit2(o[ni][0] * f0, o[ni][1] * f0);
        g_AOs[(size_t)(tb + r1) * 512 + cp] = bfsplit2(o[ni][2] * f1, o[ni][3] * f1);
    }
}

// ---------------- aux loss ----------------
__global__ void k_aux(float* __restrict__ out) {
    float aux = 0.f;
    for (int router = 0; router < 3; router++) {
        float s = 0.f;
        for (int j = 0; j < 16; j++) {
            float mp = g_rsum[router * 16 + j] / (float)(Pn * TOK);
            s += mp * mp;
        }
        aux += 16.f * s;
    }
    out[(size_t)TOK * Dn] = aux;
}

// ---------------- launch ----------------
extern "C" void kernel_launch(void* const* d_in, const int* in_sizes, int n_in,
                              void* d_out, int out_size) {
    const float* x       = (const float*)d_in[0];
    const float* wQ      = (const float*)d_in[1];
    const float* wK      = (const float*)d_in[2];
    const float* wV      = (const float*)d_in[3];
    const float* fneu    = (const float*)d_in[4];
    const float* rneu    = (const float*)d_in[5];
    const float* fqk_emb = (const float*)d_in[6];
    const float* fv_emb  = (const float*)d_in[7];
    const float* Wp_qk   = (const float*)d_in[8];
    const float* bp_qk   = (const float*)d_in[9];
    const float* Wp_v    = (const float*)d_in[10];
    const float* bp_v    = (const float*)d_in[11];
    const float* Wr_qk   = (const float*)d_in[12];
    const float* Wr_v    = (const float*)d_in[13];
    const float* W_O     = (const float*)d_in[14];
    float* out = (float*)d_out;

    // unconditional, idempotent
    cudaFuncSetAttribute(k_mma<0>,  cudaFuncAttributeMaxDynamicSharedMemorySize, GEMM_SMEM);
    cudaFuncSetAttribute(k_mma<12>, cudaFuncAttributeMaxDynamicSharedMemorySize, GEMM_SMEM);
    cudaFuncSetAttribute(k_mma<3>,  cudaFuncAttributeMaxDynamicSharedMemorySize, GEMM_SMEM);
    cudaFuncSetAttribute(k_flashmma, cudaFuncAttributeMaxDynamicSharedMemorySize, FLASH_SMEM);

    k_prep<<<2048, 256>>>(fneu);
    k_split<0><<<(TOK * 512) / 256, 256>>>(x, TOK * 512);
    k_split<1><<<(256 * 1024) / 256, 256>>>(rneu, 256 * 1024);
    k_split<2><<<(512 * 1024) / 256, 256>>>(W_O, 512 * 1024);
    // all_h = X @ Fall
    k_mma<0><<<dim3(8, 32), 256, GEMM_SMEM>>>(nullptr);
    k_router<<<TOK, 128>>>(wQ, wK, wV, fqk_emb, fv_emb, Wp_qk, bp_qk, Wp_v, bp_v, Wr_qk, Wr_v);
    // Q,K,V = C @ r  (merged; V packed in epilogue)
    k_mma<12><<<dim3(8, 96), 256, GEMM_SMEM>>>(nullptr);
    k_flashmma<<<dim3(Sn / 128, Bn * 16), 256, FLASH_SMEM>>>();
    // out = AO @ W_O
    k_mma<3><<<dim3(8, 32), 256, GEMM_SMEM>>>(out);
    if (out_size > TOK * Dn) k_aux<<<1, 1>>>(out);
}

// round 14
// speedup vs baseline: 1.0283x; 1.0283x over previous
#include <cuda_runtime.h>
#include <cuda_bf16.h>
#include <math.h>
#include <stdint.h>

// ---------------- problem constants ----------------
#define Pn 2
#define Bn 2
#define Sn 2048
#define Dn 1024
#define TOK 4096

// ---------------- scratch: packed bf16x2 split planes (uint2 = {hi-pair, lo-pair}) ----------------
__device__ __align__(16) uint2 g_Xs[(size_t)TOK*512];       // x, d-pair packed
__device__ __align__(16) uint2 g_Falls[(size_t)512*1024];   // f_neurons^T, d(k)-pair packed
__device__ __align__(16) uint2 g_Rs[(size_t)256*1024];      // r_neurons (qk|v), k-pair packed
__device__ __align__(16) uint2 g_WOs[(size_t)512*1024];     // W_O, k-pair packed
__device__ __align__(16) uint2 g_Cs[(size_t)3*TOK*128];     // CQ|CK|CV, k-pair packed
__device__ __align__(16) uint2 g_Qpk[(size_t)TOK*512];      // Q, d-pair packed
__device__ __align__(16) uint2 g_Kpk[(size_t)TOK*512];      // K, d-pair packed
__device__ __align__(16) uint2 g_Vpk[(size_t)(TOK/2)*1024]; // V, key-pair packed
__device__ __align__(16) uint2 g_AOs[(size_t)TOK*512];      // attn out, d-pair packed
__device__ __align__(16) float g_AH[(size_t)TOK*Dn];        // all_h (router input)
__device__ __align__(16) float g_Vf[(size_t)TOK*Dn];        // V float (pack input)
__device__ float g_qsq[TOK];                                // |Q|^2 partials
__device__ float g_rsum[48];

// ---------------- helpers ----------------
__device__ __forceinline__ uint32_t bf16bits(float x) {
    __nv_bfloat16 h = __float2bfloat16_rn(x);
    return (uint32_t)*reinterpret_cast<uint16_t*>(&h);
}
__device__ __forceinline__ float bf16val(uint32_t b) {
    uint16_t u = (uint16_t)b;
    __nv_bfloat16 h = *reinterpret_cast<__nv_bfloat16*>(&u);
    return __bfloat162float(h);
}
__device__ __forceinline__ uint2 bfsplit2(float a, float b) {
    uint32_t ha = bf16bits(a), hb = bf16bits(b);
    uint32_t la = bf16bits(a - bf16val(ha));
    uint32_t lb = bf16bits(b - bf16val(hb));
    return make_uint2(ha | (hb << 16), la | (lb << 16));
}
__device__ __forceinline__ void mma_bf16(float* d, const uint32_t* a, uint32_t b0, uint32_t b1) {
    asm volatile("mma.sync.aligned.m16n8k16.row.col.f32.bf16.bf16.f32 "
                 "{%0,%1,%2,%3},{%4,%5,%6,%7},{%8,%9},{%0,%1,%2,%3};"
                 : "+f"(d[0]), "+f"(d[1]), "+f"(d[2]), "+f"(d[3])
                 : "r"(a[0]), "r"(a[1]), "r"(a[2]), "r"(a[3]), "r"(b0), "r"(b1));
}
__device__ __forceinline__ void cpa16(void* smem, const void* gmem) {
    uint32_t s = (uint32_t)__cvta_generic_to_shared(smem);
    asm volatile("cp.async.cg.shared.global [%0], [%1], 16;" :: "r"(s), "l"(gmem) : "memory");
}
__device__ __forceinline__ void cpcommit() { asm volatile("cp.async.commit_group;" ::: "memory"); }
template<int N>
__device__ __forceinline__ void cpwaitN() { asm volatile("cp.async.wait_group %0;" :: "n"(N) : "memory"); }

// ---------------- prep: transpose+split f_neurons, zero accumulators ----------------
__global__ void k_prep(const float* __restrict__ fneu) {
    int idx = blockIdx.x * blockDim.x + threadIdx.x;
    if (blockIdx.x == 0 && threadIdx.x < 48) g_rsum[threadIdx.x] = 0.f;
    if (idx < TOK) g_qsq[idx] = 0.f;
    if (idx < 512 * 1024) {
        int d2 = idx >> 10, c = idx & 1023;
        int n = c >> 4, r = c & 15;
        float v0 = fneu[((size_t)n * 1024 + 2 * d2) * 16 + r];
        float v1 = fneu[((size_t)n * 1024 + 2 * d2 + 1) * 16 + r];
        g_Falls[idx] = bfsplit2(v0, v1);
    }
}

// ---------------- split kernels ----------------
template<int W>
__global__ void k_split(const float* __restrict__ src, int n) {
    int idx = blockIdx.x * blockDim.x + threadIdx.x;
    if (idx >= n) return;
    if (W == 0) {
        float2 v = *reinterpret_cast<const float2*>(src + (size_t)2 * idx);
        g_Xs[idx] = bfsplit2(v.x, v.y);
    }
    if (W == 1) {
        int k2 = idx >> 10, c = idx & 1023;
        g_Rs[idx] = bfsplit2(src[(size_t)2 * k2 * 1024 + c], src[(size_t)(2 * k2 + 1) * 1024 + c]);
    }
    if (W == 2) {
        int k2 = idx >> 10, c = idx & 1023;
        g_WOs[idx] = bfsplit2(src[(size_t)2 * k2 * 1024 + c], src[(size_t)(2 * k2 + 1) * 1024 + c]);
    }
}

// pack V: key-pair packed planes (coalesced)
__global__ void k_packV() {
    int idx = blockIdx.x * blockDim.x + threadIdx.x;
    if (idx >= 2048 * 1024) return;
    int row2 = idx >> 10, d = idx & 1023;
    int b = row2 >> 10, kl = row2 & 1023;
    size_t tok = (size_t)b * 2048 + 2 * kl;
    g_Vpk[idx] = bfsplit2(g_Vf[tok * 1024 + d], g_Vf[(tok + 1) * 1024 + d]);
}

// ---------------- 3xbf16 GEMM, 3-stage cp.async pipeline ----------------
// block tile 128x128x16, 8 warps (4x2). Operands pre-split bf16-packed (uint2).
// MODE 0: AH = X @ Fall.  MODE 12: QKV = C @ r (grid y=96).  MODE 3: out = AO @ W_O.
#define AS2 12    /* As row stride in uint2 */
#define BS2 132   /* Bs row stride in uint2 */
#define GEMM_SMEM ((3*128*AS2 + 3*8*BS2) * 8)
template<int MODE>
__global__ __launch_bounds__(256) void k_mma(float* __restrict__ extC) {
    constexpr int K2 = (MODE == 12) ? 128 : 512;   // k-pairs per row
    constexpr int N = 1024;
    constexpr int NIT = K2 / 8;

    const uint2* A; const uint2* B;
    if (MODE == 0)  { A = g_Xs;  B = g_Falls; }
    if (MODE == 12) { A = g_Cs;  B = (blockIdx.y < 64) ? g_Rs : (g_Rs + (size_t)128 * 1024); }
    if (MODE == 3)  { A = g_AOs; B = g_WOs; }

    extern __shared__ uint2 sm[];
    uint2* As = sm;                    // [3][128][AS2]
    uint2* Bs = sm + 3 * 128 * AS2;    // [3][8][BS2]

    const int tid  = threadIdx.x;
    const int lane = tid & 31;
    const int warp = tid >> 5;
    const int wr = warp >> 1;
    const int wc = warp & 1;
    const int g = lane >> 2;
    const int t = lane & 3;
    const int bx = blockIdx.x, by = blockIdx.y;

    float acc[2][8][4];
    #pragma unroll
    for (int mi = 0; mi < 2; mi++)
        #pragma unroll
        for (int ni = 0; ni < 8; ni++)
            #pragma unroll
            for (int j = 0; j < 4; j++) acc[mi][ni][j] = 0.f;

    const uint2* Ab = A + (size_t)by * 128 * K2;
    const uint2* Bb = B + (size_t)bx * 128;

    auto loadStage = [&](int st, int k20) {
        #pragma unroll
        for (int i = 0; i < 2; i++) {
            int chunk = tid + i * 256;
            int r = chunk >> 2, cc = (chunk & 3) * 2;
            cpa16(&As[(st * 128 + r) * AS2 + cc], Ab + (size_t)r * K2 + k20 + cc);
        }
        #pragma unroll
        for (int i = 0; i < 2; i++) {
            int chunk = tid + i * 256;
            int kr = chunk >> 6, cc = (chunk & 63) * 2;
            cpa16(&Bs[(st * 8 + kr) * BS2 + cc], Bb + (size_t)(k20 + kr) * N + cc);
        }
    };

    loadStage(0, 0); cpcommit();
    loadStage(1, 8); cpcommit();

    for (int it = 0; it < NIT; it++) {
        if (it + 1 < NIT) cpwaitN<1>(); else cpwaitN<0>();
        __syncthreads();
        if (it + 2 < NIT) { loadStage((it + 2) % 3, (it + 2) * 8); cpcommit(); }

        const int st = it % 3;
        uint32_t ah[2][4], al[2][4];
        #pragma unroll
        for (int mi = 0; mi < 2; mi++) {
            int r0 = wr * 32 + mi * 16 + g;
            uint2 a0 = As[(st * 128 + r0) * AS2 + t];
            uint2 a1 = As[(st * 128 + r0 + 8) * AS2 + t];
            uint2 a2 = As[(st * 128 + r0) * AS2 + t + 4];
            uint2 a3 = As[(st * 128 + r0 + 8) * AS2 + t + 4];
            ah[mi][0] = a0.x; ah[mi][1] = a1.x; ah[mi][2] = a2.x; ah[mi][3] = a3.x;
            al[mi][0] = a0.y; al[mi][1] = a1.y; al[mi][2] = a2.y; al[mi][3] = a3.y;
        }
        #pragma unroll
        for (int ni = 0; ni < 8; ni++) {
            int c = wc * 64 + ni * 8 + g;
            uint2 b0 = Bs[(st * 8 + t) * BS2 + c];
            uint2 b1 = Bs[(st * 8 + t + 4) * BS2 + c];
            #pragma unroll
            for (int mi = 0; mi < 2; mi++) {
                mma_bf16(acc[mi][ni], ah[mi], b0.x, b1.x);
                mma_bf16(acc[mi][ni], al[mi], b0.x, b1.x);
                mma_bf16(acc[mi][ni], ah[mi], b0.y, b1.y);
            }
        }
    }

    // epilogue
    #pragma unroll
    for (int mi = 0; mi < 2; mi++) {
        int r0 = by * 128 + wr * 32 + mi * 16 + g;
        float qs0 = 0.f, qs1 = 0.f;
        #pragma unroll
        for (int ni = 0; ni < 8; ni++) {
            int c = bx * 128 + wc * 64 + ni * 8 + 2 * t;
            int cp = c >> 1;
            float v0 = acc[mi][ni][0], v1 = acc[mi][ni][1];
            float v2 = acc[mi][ni][2], v3 = acc[mi][ni][3];
            if (MODE == 0) {
                *reinterpret_cast<float2*>(g_AH + (size_t)r0 * N + c) = make_float2(v0, v1);
                *reinterpret_cast<float2*>(g_AH + (size_t)(r0 + 8) * N + c) = make_float2(v2, v3);
            }
            if (MODE == 3) {
                *reinterpret_cast<float2*>(extC + (size_t)r0 * N + c) = make_float2(v0, v1);
                *reinterpret_cast<float2*>(extC + (size_t)(r0 + 8) * N + c) = make_float2(v2, v3);
            }
            if (MODE == 12) {
                if (r0 < TOK) {            // Q rows
                    qs0 += v0 * v0 + v1 * v1;
                    qs1 += v2 * v2 + v3 * v3;
                    g_Qpk[(size_t)r0 * 512 + cp] = bfsplit2(v0, v1);
                    g_Qpk[(size_t)(r0 + 8) * 512 + cp] = bfsplit2(v2, v3);
                } else if (r0 < 2 * TOK) { // K rows
                    g_Kpk[(size_t)(r0 - TOK) * 512 + cp] = bfsplit2(v0, v1);
                    g_Kpk[(size_t)(r0 + 8 - TOK) * 512 + cp] = bfsplit2(v2, v3);
                } else {                   // V rows: float out, packed later (coalesced)
                    *reinterpret_cast<float2*>(g_Vf + (size_t)(r0 - 2 * TOK) * N + c) = make_float2(v0, v1);
                    *reinterpret_cast<float2*>(g_Vf + (size_t)(r0 + 8 - 2 * TOK) * N + c) = make_float2(v2, v3);
                }
            }
        }
        if (MODE == 12 && r0 < TOK) {
            atomicAdd(&g_qsq[r0], qs0);
            atomicAdd(&g_qsq[r0 + 8], qs1);
        }
    }
}

// ---------------- per-token router / coefficient kernel ----------------
__global__ __launch_bounds__(128) void k_router(
    const float* __restrict__ wQg, const float* __restrict__ wKg, const float* __restrict__ wVg,
    const float* __restrict__ fqk_emb, const float* __restrict__ fv_emb,
    const float* __restrict__ Wp_qk, const float* __restrict__ bp_qk,
    const float* __restrict__ Wp_v, const float* __restrict__ bp_v,
    const float* __restrict__ Wr_qk, const float* __restrict__ Wr_v)
{
    const int t = blockIdx.x;
    const int tid = threadIdx.x;
    __shared__ float AHs[Dn];
    __shared__ float gate[3][32];
    __shared__ float hs[3][16];
    __shared__ float ins[3][128];
    __shared__ float lg[3][16];
    __shared__ float wsm[3][16];
    __shared__ float cbuf[768];

    for (int i = tid; i < Dn; i += 128) AHs[i] = g_AH[(size_t)t * Dn + i];

    float cacc[6] = {0.f, 0.f, 0.f, 0.f, 0.f, 0.f};
    float sumAcc = 0.f;

    for (int p = 0; p < Pn; p++) {
        __syncthreads();
        if (tid < 96) {
            int router = tid >> 5, n = tid & 31;
            const float* src = (router == 0) ? wQg : ((router == 1) ? wKg : wVg);
            gate[router][n] = src[((size_t)p * TOK + t) * 32 + n];
        }
        __syncthreads();
        if (tid < 48) {
            int router = tid >> 4, r = tid & 15;
            int base = (router == 2) ? 512 : 0;
            float a = 0.f;
            #pragma unroll
            for (int n = 0; n < 32; n++) a += gate[router][n] * AHs[base + n * 16 + r];
            hs[router][r] = a;
        }
        __syncthreads();
        for (int v = tid; v < 384; v += 128) {
            int router = v >> 7, i = v & 127;
            float val;
            if (i < 64) {
                const float* Wp = (router == 2) ? Wp_v : Wp_qk;
                const float* bp = (router == 2) ? bp_v : bp_qk;
                float a = bp[i];
                #pragma unroll
                for (int r = 0; r < 16; r++) a += hs[router][r] * Wp[r * 64 + i];
                val = a;
            } else {
                int d = i - 64;
                const float* emb = (router == 2) ? fv_emb : fqk_emb;
                float a = 0.f;
                #pragma unroll
                for (int n = 0; n < 32; n++) a += gate[router][n] * emb[n * 64 + d];
                val = a;
            }
            ins[router][i] = val;
        }
        __syncthreads();
        if (tid < 48) {
            int router = tid >> 4, j = tid & 15;
            const float* Wr = (router == 2) ? Wr_v : Wr_qk;
            float a = 0.f;
            for (int i = 0; i < 128; i++) a += ins[router][i] * Wr[i * 16 + j];
            lg[router][j] = a;
        }
        __syncthreads();
        if (tid < 3) {
            float mx = -1e30f;
            for (int j = 0; j < 16; j++) mx = fmaxf(mx, lg[tid][j]);
            float e[16], s = 0.f;
            for (int j = 0; j < 16; j++) { e[j] = __expf(lg[tid][j] - mx); s += e[j]; }
            float inv = 1.f / s;
            for (int j = 0; j < 16; j++) wsm[tid][j] = e[j] * inv;
        }
        __syncthreads();
        if (tid < 48) sumAcc += wsm[tid >> 4][tid & 15];
        #pragma unroll
        for (int it = 0; it < 6; it++) {
            int v = tid + it * 128;
            int router = v >> 8, idx = v & 255;
            cacc[it] += wsm[router][idx >> 4] * hs[router][idx & 15];
        }
    }
    #pragma unroll
    for (int it = 0; it < 6; it++) cbuf[tid + it * 128] = cacc[it];
    __syncthreads();
    for (int j = tid; j < 384; j += 128) {
        int router = j >> 7, j2 = j & 127;
        g_Cs[((size_t)router * TOK + t) * 128 + j2] =
            bfsplit2(cbuf[router * 256 + 2 * j2], cbuf[router * 256 + 2 * j2 + 1]);
    }
    if (tid < 48) atomicAdd(&g_rsum[tid], sumAcc);
}

// ---------------- 3xbf16 flash attention, 3-stage cp.async pipeline ----------------
// grid (S/128, B*H), 256 threads (8 warps), warp = 16 q rows, KV tile = 32.
#define KS2 36   /* K row stride in uint2 */
#define VS2 68   /* V row stride in uint2 */
#define FLASH_SMEM ((3*32*KS2 + 3*16*VS2) * 8)
__global__ __launch_bounds__(256) void k_flashmma() {
    extern __shared__ uint2 fsm[];
    uint2* Ks = fsm;                   // [3][32][KS2]
    uint2* Vs = fsm + 3 * 32 * KS2;    // [3][16][VS2]

    const int qt = blockIdx.x;
    const int bh = blockIdx.y;
    const int b = bh >> 4, h = bh & 15;
    const int tid = threadIdx.x;
    const int lane = tid & 31;
    const int warp = tid >> 5;
    const int g = lane >> 2, t = lane & 3;
    const int q0 = qt * 128 + warp * 16;

    uint32_t qh[4][4], ql[4][4];
    {
        const uint2* Qr0 = g_Qpk + (size_t)(b * Sn + q0 + g) * 512 + h * 32;
        const uint2* Qr1 = g_Qpk + (size_t)(b * Sn + q0 + g + 8) * 512 + h * 32;
        #pragma unroll
        for (int kc = 0; kc < 4; kc++) {
            uint2 a0 = Qr0[kc * 8 + t];
            uint2 a1 = Qr1[kc * 8 + t];
            uint2 a2 = Qr0[kc * 8 + t + 4];
            uint2 a3 = Qr1[kc * 8 + t + 4];
            qh[kc][0] = a0.x; qh[kc][1] = a1.x; qh[kc][2] = a2.x; qh[kc][3] = a3.x;
            ql[kc][0] = a0.y; ql[kc][1] = a1.y; ql[kc][2] = a2.y; ql[kc][3] = a3.y;
        }
    }

    float o[8][4];
    #pragma unroll
    for (int ni = 0; ni < 8; ni++)
        #pragma unroll
        for (int j = 0; j < 4; j++) o[ni][j] = 0.f;
    float m0 = -1e30f, m1 = -1e30f, l0 = 0.f, l1 = 0.f;

    const int nkt = 4 * qt + 4;

    auto loadKV = [&](int st, int kt) {
        #pragma unroll
        for (int i = 0; i < 4; i++) {
            int chunk = tid + i * 256;
            if (chunk < 512) {
                int r = chunk >> 4, cc = (chunk & 15) * 2;
                cpa16(&Ks[(st * 32 + r) * KS2 + cc],
                      g_Kpk + (size_t)(b * Sn + kt * 32 + r) * 512 + h * 32 + cc);
            } else {
                int c2 = chunk - 512;
                int r = c2 >> 5, cc = (c2 & 31) * 2;
                cpa16(&Vs[(st * 16 + r) * VS2 + cc],
                      g_Vpk + (size_t)(b * (Sn / 2) + kt * 16 + r) * 1024 + h * 64 + cc);
            }
        }
    };

    loadKV(0, 0); cpcommit();
    loadKV(1, 1); cpcommit();

    for (int kt = 0; kt < nkt; kt++) {
        if (kt + 1 < nkt) cpwaitN<1>(); else cpwaitN<0>();
        __syncthreads();
        if (kt + 2 < nkt) { loadKV((kt + 2) % 3, kt + 2); cpcommit(); }

        if (kt * 32 > q0 + 15) continue;   // fully masked for this warp
        const int st = kt % 3;

        float s[4][4];
        #pragma unroll
        for (int ni = 0; ni < 4; ni++)
            #pragma unroll
            for (int j = 0; j < 4; j++) s[ni][j] = 0.f;
        #pragma unroll
        for (int kc = 0; kc < 4; kc++) {
            #pragma unroll
            for (int ni = 0; ni < 4; ni++) {
                uint2 b0 = Ks[(st * 32 + ni * 8 + g) * KS2 + kc * 8 + t];
                uint2 b1 = Ks[(st * 32 + ni * 8 + g) * KS2 + kc * 8 + t + 4];
                mma_bf16(s[ni], qh[kc], b0.x, b1.x);
                mma_bf16(s[ni], ql[kc], b0.x, b1.x);
                mma_bf16(s[ni], qh[kc], b0.y, b1.y);
            }
        }
        #pragma unroll
        for (int ni = 0; ni < 4; ni++)
            #pragma unroll
            for (int j = 0; j < 4; j++) s[ni][j] *= 0.125f;

        if (kt * 32 + 31 > q0) {
            const int r0 = q0 + g, r1 = r0 + 8, cb = kt * 32;
            #pragma unroll
            for (int ni = 0; ni < 4; ni++) {
                int c0 = cb + ni * 8 + 2 * t;
                if (c0 > r0)     s[ni][0] = -1e30f;
                if (c0 + 1 > r0) s[ni][1] = -1e30f;
                if (c0 > r1)     s[ni][2] = -1e30f;
                if (c0 + 1 > r1) s[ni][3] = -1e30f;
            }
        }

        float mx0 = -1e30f, mx1 = -1e30f;
        #pragma unroll
        for (int ni = 0; ni < 4; ni++) {
            mx0 = fmaxf(mx0, fmaxf(s[ni][0], s[ni][1]));
            mx1 = fmaxf(mx1, fmaxf(s[ni][2], s[ni][3]));
        }
        mx0 = fmaxf(mx0, __shfl_xor_sync(0xffffffffu, mx0, 1));
        mx0 = fmaxf(mx0, __shfl_xor_sync(0xffffffffu, mx0, 2));
        mx1 = fmaxf(mx1, __shfl_xor_sync(0xffffffffu, mx1, 1));
        mx1 = fmaxf(mx1, __shfl_xor_sync(0xffffffffu, mx1, 2));
        float mn0 = fmaxf(m0, mx0), mn1 = fmaxf(m1, mx1);
        float cr0 = __expf(m0 - mn0), cr1 = __expf(m1 - mn1);
        m0 = mn0; m1 = mn1;
        #pragma unroll
        for (int ni = 0; ni < 8; ni++) {
            o[ni][0] *= cr0; o[ni][1] *= cr0;
            o[ni][2] *= cr1; o[ni][3] *= cr1;
        }

        float rs0 = 0.f, rs1 = 0.f;
        #pragma unroll
        for (int ni = 0; ni < 4; ni++) {
            s[ni][0] = __expf(s[ni][0] - m0);
            s[ni][1] = __expf(s[ni][1] - m0);
            s[ni][2] = __expf(s[ni][2] - m1);
            s[ni][3] = __expf(s[ni][3] - m1);
            rs0 += s[ni][0] + s[ni][1];
            rs1 += s[ni][2] + s[ni][3];
        }
        rs0 += __shfl_xor_sync(0xffffffffu, rs0, 1);
        rs0 += __shfl_xor_sync(0xffffffffu, rs0, 2);
        rs1 += __shfl_xor_sync(0xffffffffu, rs1, 1);
        rs1 += __shfl_xor_sync(0xffffffffu, rs1, 2);
        l0 = l0 * cr0 + rs0;
        l1 = l1 * cr1 + rs1;

        // P@V: C-fragment == A-fragment layout for bf16 — no shuffles
        #pragma unroll
        for (int kc = 0; kc < 2; kc++) {
            uint32_t pH[4], pL[4];
            uint2 f0 = bfsplit2(s[2 * kc][0], s[2 * kc][1]);
            uint2 f1 = bfsplit2(s[2 * kc][2], s[2 * kc][3]);
            uint2 f2 = bfsplit2(s[2 * kc + 1][0], s[2 * kc + 1][1]);
            uint2 f3 = bfsplit2(s[2 * kc + 1][2], s[2 * kc + 1][3]);
            pH[0] = f0.x; pH[1] = f1.x; pH[2] = f2.x; pH[3] = f3.x;
            pL[0] = f0.y; pL[1] = f1.y; pL[2] = f2.y; pL[3] = f3.y;
            #pragma unroll
            for (int ni = 0; ni < 8; ni++) {
                uint2 b0 = Vs[(st * 16 + kc * 8 + t) * VS2 + ni * 8 + g];
                uint2 b1 = Vs[(st * 16 + kc * 8 + t + 4) * VS2 + ni * 8 + g];
                mma_bf16(o[ni], pH, b0.x, b1.x);
                mma_bf16(o[ni], pL, b0.x, b1.x);
                mma_bf16(o[ni], pH, b0.y, b1.y);
            }
        }
    }

    // epilogue: normalize, q-norm scale (from g_qsq), write packed AO
    const int r0 = q0 + g, r1 = r0 + 8;
    const int tb = b * Sn;
    float qsq0 = g_qsq[tb + r0], qsq1 = g_qsq[tb + r1];
    float sc0 = (qsq0 > 1e-12f) ? 1.f : sqrtf(qsq0) * 1e-6f;
    float sc1 = (qsq1 > 1e-12f) ? 1.f : sqrtf(qsq1) * 1e-6f;
    float f0 = sc0 / l0;
    float f1 = sc1 / l1;
    #pragma unroll
    for (int ni = 0; ni < 8; ni++) {
        int cp = h * 32 + ni * 4 + t;
        g_AOs[(size_t)(tb + r0) * 512 + cp] = bfsplit2(o[ni][0] * f0, o[ni][1] * f0);
        g_AOs[(size_t)(tb + r1) * 512 + cp] = bfsplit2(o[ni][2] * f1, o[ni][3] * f1);
    }
}

// ---------------- aux loss ----------------
__global__ void k_aux(float* __restrict__ out) {
    float aux = 0.f;
    for (int router = 0; router < 3; router++) {
        float s = 0.f;
        for (int j = 0; j < 16; j++) {
            float mp = g_rsum[router * 16 + j] / (float)(Pn * TOK);
            s += mp * mp;
        }
        aux += 16.f * s;
    }
    out[(size_t)TOK * Dn] = aux;
}

// ---------------- launch ----------------
// Launch order keeps k_mma<0> at profiled slot (index 3); k_split<2> (W_O)
// deferred to slot 8 — its only consumer is k_mma<3> at slot 9.
extern "C" void kernel_launch(void* const* d_in, const int* in_sizes, int n_in,
                              void* d_out, int out_size) {
    const float* x       = (const float*)d_in[0];
    const float* wQ      = (const float*)d_in[1];
    const float* wK      = (const float*)d_in[2];
    const float* wV      = (const float*)d_in[3];
    const float* fneu    = (const float*)d_in[4];
    const float* rneu    = (const float*)d_in[5];
    const float* fqk_emb = (const float*)d_in[6];
    const float* fv_emb  = (const float*)d_in[7];
    const float* Wp_qk   = (const float*)d_in[8];
    const float* bp_qk   = (const float*)d_in[9];
    const float* Wp_v    = (const float*)d_in[10];
    const float* bp_v    = (const float*)d_in[11];
    const float* Wr_qk   = (const float*)d_in[12];
    const float* Wr_v    = (const float*)d_in[13];
    const float* W_O     = (const float*)d_in[14];
    float* out = (float*)d_out;

    // unconditional, idempotent
    cudaFuncSetAttribute(k_mma<0>,  cudaFuncAttributeMaxDynamicSharedMemorySize, GEMM_SMEM);
    cudaFuncSetAttribute(k_mma<12>, cudaFuncAttributeMaxDynamicSharedMemorySize, GEMM_SMEM);
    cudaFuncSetAttribute(k_mma<3>,  cudaFuncAttributeMaxDynamicSharedMemorySize, GEMM_SMEM);
    cudaFuncSetAttribute(k_flashmma, cudaFuncAttributeMaxDynamicSharedMemorySize, FLASH_SMEM);

    k_prep<<<2048, 256>>>(fneu);                               // 0
    k_split<0><<<(TOK * 512) / 256, 256>>>(x, TOK * 512);      // 1
    k_split<1><<<(256 * 1024) / 256, 256>>>(rneu, 256 * 1024); // 2
    k_mma<0><<<dim3(8, 32), 256, GEMM_SMEM>>>(nullptr);        // 3  <-- profiled
    k_router<<<TOK, 128>>>(wQ, wK, wV, fqk_emb, fv_emb, Wp_qk, bp_qk, Wp_v, bp_v, Wr_qk, Wr_v); // 4
    k_mma<12><<<dim3(8, 96), 256, GEMM_SMEM>>>(nullptr);       // 5
    k_packV<<<(2048 * 1024) / 256, 256>>>();                   // 6
    k_flashmma<<<dim3(Sn / 128, Bn * 16), 256, FLASH_SMEM>>>();// 7
    k_split<2><<<(512 * 1024) / 256, 256>>>(W_O, 512 * 1024);  // 8
    k_mma<3><<<dim3(8, 32), 256, GEMM_SMEM>>>(out);            // 9
    if (out_size > TOK * Dn) k_aux<<<1, 1>>>(out);             // 10
}

// round 15
// speedup vs baseline: 1.0313x; 1.0030x over previous
#include <cuda_runtime.h>
#include <cuda_bf16.h>
#include <math.h>
#include <stdint.h>

// ---------------- problem constants ----------------
#define Pn 2
#define Bn 2
#define Sn 2048
#define Dn 1024
#define TOK 4096

// ---------------- scratch: packed bf16x2 split planes (uint2 = {hi-pair, lo-pair}) ----------------
__device__ __align__(16) uint2 g_Xs[(size_t)TOK*512];       // x, d-pair packed
__device__ __align__(16) uint2 g_Falls[(size_t)512*1024];   // f_neurons^T, d(k)-pair packed
__device__ __align__(16) uint2 g_Rs[(size_t)256*1024];      // r_neurons (qk|v), k-pair packed
__device__ __align__(16) uint2 g_WOs[(size_t)512*1024];     // W_O, k-pair packed
__device__ __align__(16) uint2 g_Cs[(size_t)3*TOK*128];     // CQ|CK|CV, k-pair packed
__device__ __align__(16) uint2 g_Qpk[(size_t)TOK*512];      // Q, d-pair packed
__device__ __align__(16) uint2 g_Kpk[(size_t)TOK*512];      // K, d-pair packed
__device__ __align__(16) uint2 g_Vpk[(size_t)(TOK/2)*1024]; // V, key-pair packed
__device__ __align__(16) uint2 g_AOs[(size_t)TOK*512];      // attn out, d-pair packed
__device__ __align__(16) float g_AH[(size_t)TOK*Dn];        // all_h (router input)
__device__ __align__(16) float g_Vf[(size_t)TOK*Dn];        // V float (pack input)
__device__ float g_qsq[TOK];                                // |Q|^2 partials
__device__ float g_rsum[48];

// ---------------- helpers ----------------
__device__ __forceinline__ uint32_t bf16bits(float x) {
    __nv_bfloat16 h = __float2bfloat16_rn(x);
    return (uint32_t)*reinterpret_cast<uint16_t*>(&h);
}
__device__ __forceinline__ float bf16val(uint32_t b) {
    uint16_t u = (uint16_t)b;
    __nv_bfloat16 h = *reinterpret_cast<__nv_bfloat16*>(&u);
    return __bfloat162float(h);
}
__device__ __forceinline__ uint2 bfsplit2(float a, float b) {
    uint32_t ha = bf16bits(a), hb = bf16bits(b);
    uint32_t la = bf16bits(a - bf16val(ha));
    uint32_t lb = bf16bits(b - bf16val(hb));
    return make_uint2(ha | (hb << 16), la | (lb << 16));
}
__device__ __forceinline__ void mma_bf16(float* d, const uint32_t* a, uint32_t b0, uint32_t b1) {
    asm volatile("mma.sync.aligned.m16n8k16.row.col.f32.bf16.bf16.f32 "
                 "{%0,%1,%2,%3},{%4,%5,%6,%7},{%8,%9},{%0,%1,%2,%3};"
                 : "+f"(d[0]), "+f"(d[1]), "+f"(d[2]), "+f"(d[3])
                 : "r"(a[0]), "r"(a[1]), "r"(a[2]), "r"(a[3]), "r"(b0), "r"(b1));
}
__device__ __forceinline__ void cpa16(void* smem, const void* gmem) {
    uint32_t s = (uint32_t)__cvta_generic_to_shared(smem);
    asm volatile("cp.async.cg.shared.global [%0], [%1], 16;" :: "r"(s), "l"(gmem) : "memory");
}
__device__ __forceinline__ void cpcommit() { asm volatile("cp.async.commit_group;" ::: "memory"); }
template<int N>
__device__ __forceinline__ void cpwaitN() { asm volatile("cp.async.wait_group %0;" :: "n"(N) : "memory"); }

// ---------------- prep: transpose+split f_neurons, zero accumulators ----------------
__global__ void k_prep(const float* __restrict__ fneu) {
    int idx = blockIdx.x * blockDim.x + threadIdx.x;
    if (blockIdx.x == 0 && threadIdx.x < 48) g_rsum[threadIdx.x] = 0.f;
    if (idx < TOK) g_qsq[idx] = 0.f;
    if (idx < 512 * 1024) {
        int d2 = idx >> 10, c = idx & 1023;
        int n = c >> 4, r = c & 15;
        float v0 = fneu[((size_t)n * 1024 + 2 * d2) * 16 + r];
        float v1 = fneu[((size_t)n * 1024 + 2 * d2 + 1) * 16 + r];
        g_Falls[idx] = bfsplit2(v0, v1);
    }
}

// ---------------- split kernels ----------------
template<int W>
__global__ void k_split(const float* __restrict__ src, int n) {
    int idx = blockIdx.x * blockDim.x + threadIdx.x;
    if (idx >= n) return;
    if (W == 0) {
        float2 v = *reinterpret_cast<const float2*>(src + (size_t)2 * idx);
        g_Xs[idx] = bfsplit2(v.x, v.y);
    }
    if (W == 1) {
        int k2 = idx >> 10, c = idx & 1023;
        g_Rs[idx] = bfsplit2(src[(size_t)2 * k2 * 1024 + c], src[(size_t)(2 * k2 + 1) * 1024 + c]);
    }
    if (W == 2) {
        int k2 = idx >> 10, c = idx & 1023;
        g_WOs[idx] = bfsplit2(src[(size_t)2 * k2 * 1024 + c], src[(size_t)(2 * k2 + 1) * 1024 + c]);
    }
}

// pack V: key-pair packed planes (coalesced)
__global__ void k_packV() {
    int idx = blockIdx.x * blockDim.x + threadIdx.x;
    if (idx >= 2048 * 1024) return;
    int row2 = idx >> 10, d = idx & 1023;
    int b = row2 >> 10, kl = row2 & 1023;
    size_t tok = (size_t)b * 2048 + 2 * kl;
    g_Vpk[idx] = bfsplit2(g_Vf[tok * 1024 + d], g_Vf[(tok + 1) * 1024 + d]);
}

// ---------------- 3xbf16 GEMM, 4-stage cp.async pipeline ----------------
// block tile 64x128x16, 8 warps (2x4), warp tile 32x32. st = it&3 (folds under unroll 4).
// MODE 0: AH = X @ Fall.  MODE 12: QKV = C @ r (grid y=192).  MODE 3: out = AO @ W_O.
#define AS2 12    /* As row stride in uint2 */
#define BS2 132   /* Bs row stride in uint2 */
#define GEMM_SMEM ((4*64*AS2 + 4*8*BS2) * 8)
template<int MODE>
__global__ __launch_bounds__(256) void k_mma(float* __restrict__ extC) {
    constexpr int K2 = (MODE == 12) ? 128 : 512;   // k-pairs per row
    constexpr int N = 1024;
    constexpr int NIT = K2 / 8;

    const uint2* A; const uint2* B;
    if (MODE == 0)  { A = g_Xs;  B = g_Falls; }
    if (MODE == 12) { A = g_Cs;  B = (blockIdx.y < 128) ? g_Rs : (g_Rs + (size_t)128 * 1024); }
    if (MODE == 3)  { A = g_AOs; B = g_WOs; }

    extern __shared__ uint2 sm[];
    uint2* As = sm;                    // [4][64][AS2]
    uint2* Bs = sm + 4 * 64 * AS2;     // [4][8][BS2]

    const int tid  = threadIdx.x;
    const int lane = tid & 31;
    const int warp = tid >> 5;
    const int wr = warp >> 2;          // 0..1
    const int wc = warp & 3;           // 0..3
    const int g = lane >> 2;
    const int t = lane & 3;
    const int bx = blockIdx.x, by = blockIdx.y;

    float acc[2][4][4];
    #pragma unroll
    for (int mi = 0; mi < 2; mi++)
        #pragma unroll
        for (int ni = 0; ni < 4; ni++)
            #pragma unroll
            for (int j = 0; j < 4; j++) acc[mi][ni][j] = 0.f;

    const uint2* Ab = A + (size_t)by * 64 * K2;
    const uint2* Bb = B + (size_t)bx * 128;

    auto loadStage = [&](int st, int k20) {
        {   // A: 64 rows x 8 pairs = 256 16B chunks, 1 per thread
            int r = tid >> 2, cc = (tid & 3) * 2;
            cpa16(&As[(st * 64 + r) * AS2 + cc], Ab + (size_t)r * K2 + k20 + cc);
        }
        #pragma unroll
        for (int i = 0; i < 2; i++) {  // B: 8 rows x 128 cols = 512 chunks, 2 per thread
            int chunk = tid + i * 256;
            int kr = chunk >> 6, cc = (chunk & 63) * 2;
            cpa16(&Bs[(st * 8 + kr) * BS2 + cc], Bb + (size_t)(k20 + kr) * N + cc);
        }
    };

    loadStage(0, 0);  cpcommit();
    loadStage(1, 8);  cpcommit();
    loadStage(2, 16); cpcommit();

    #pragma unroll 4
    for (int it = 0; it < NIT; it++) {
        if (it + 2 < NIT) cpwaitN<2>();
        else if (it + 1 < NIT) cpwaitN<1>();
        else cpwaitN<0>();
        __syncthreads();
        if (it + 3 < NIT) { loadStage((it + 3) & 3, (it + 3) * 8); cpcommit(); }

        const int st = it & 3;
        uint32_t ah[2][4], al[2][4];
        #pragma unroll
        for (int mi = 0; mi < 2; mi++) {
            int r0 = wr * 32 + mi * 16 + g;
            uint2 a0 = As[(st * 64 + r0) * AS2 + t];
            uint2 a1 = As[(st * 64 + r0 + 8) * AS2 + t];
            uint2 a2 = As[(st * 64 + r0) * AS2 + t + 4];
            uint2 a3 = As[(st * 64 + r0 + 8) * AS2 + t + 4];
            ah[mi][0] = a0.x; ah[mi][1] = a1.x; ah[mi][2] = a2.x; ah[mi][3] = a3.x;
            al[mi][0] = a0.y; al[mi][1] = a1.y; al[mi][2] = a2.y; al[mi][3] = a3.y;
        }
        #pragma unroll
        for (int ni = 0; ni < 4; ni++) {
            int c = wc * 32 + ni * 8 + g;
            uint2 b0 = Bs[(st * 8 + t) * BS2 + c];
            uint2 b1 = Bs[(st * 8 + t + 4) * BS2 + c];
            #pragma unroll
            for (int mi = 0; mi < 2; mi++) {
                mma_bf16(acc[mi][ni], ah[mi], b0.x, b1.x);
                mma_bf16(acc[mi][ni], al[mi], b0.x, b1.x);
                mma_bf16(acc[mi][ni], ah[mi], b0.y, b1.y);
            }
        }
    }

    // epilogue
    #pragma unroll
    for (int mi = 0; mi < 2; mi++) {
        int r0 = by * 64 + wr * 32 + mi * 16 + g;
        float qs0 = 0.f, qs1 = 0.f;
        #pragma unroll
        for (int ni = 0; ni < 4; ni++) {
            int c = bx * 128 + wc * 32 + ni * 8 + 2 * t;
            int cp = c >> 1;
            float v0 = acc[mi][ni][0], v1 = acc[mi][ni][1];
            float v2 = acc[mi][ni][2], v3 = acc[mi][ni][3];
            if (MODE == 0) {
                *reinterpret_cast<float2*>(g_AH + (size_t)r0 * N + c) = make_float2(v0, v1);
                *reinterpret_cast<float2*>(g_AH + (size_t)(r0 + 8) * N + c) = make_float2(v2, v3);
            }
            if (MODE == 3) {
                *reinterpret_cast<float2*>(extC + (size_t)r0 * N + c) = make_float2(v0, v1);
                *reinterpret_cast<float2*>(extC + (size_t)(r0 + 8) * N + c) = make_float2(v2, v3);
            }
            if (MODE == 12) {
                if (r0 < TOK) {            // Q rows
                    qs0 += v0 * v0 + v1 * v1;
                    qs1 += v2 * v2 + v3 * v3;
                    g_Qpk[(size_t)r0 * 512 + cp] = bfsplit2(v0, v1);
                    g_Qpk[(size_t)(r0 + 8) * 512 + cp] = bfsplit2(v2, v3);
                } else if (r0 < 2 * TOK) { // K rows
                    g_Kpk[(size_t)(r0 - TOK) * 512 + cp] = bfsplit2(v0, v1);
                    g_Kpk[(size_t)(r0 + 8 - TOK) * 512 + cp] = bfsplit2(v2, v3);
                } else {                   // V rows: float out, packed later (coalesced)
                    *reinterpret_cast<float2*>(g_Vf + (size_t)(r0 - 2 * TOK) * N + c) = make_float2(v0, v1);
                    *reinterpret_cast<float2*>(g_Vf + (size_t)(r0 + 8 - 2 * TOK) * N + c) = make_float2(v2, v3);
                }
            }
        }
        if (MODE == 12 && r0 < TOK) {
            atomicAdd(&g_qsq[r0], qs0);
            atomicAdd(&g_qsq[r0 + 8], qs1);
        }
    }
}

// ---------------- per-token router / coefficient kernel ----------------
__global__ __launch_bounds__(128) void k_router(
    const float* __restrict__ wQg, const float* __restrict__ wKg, const float* __restrict__ wVg,
    const float* __restrict__ fqk_emb, const float* __restrict__ fv_emb,
    const float* __restrict__ Wp_qk, const float* __restrict__ bp_qk,
    const float* __restrict__ Wp_v, const float* __restrict__ bp_v,
    const float* __restrict__ Wr_qk, const float* __restrict__ Wr_v)
{
    const int t = blockIdx.x;
    const int tid = threadIdx.x;
    __shared__ float AHs[Dn];
    __shared__ float gate[3][32];
    __shared__ float hs[3][16];
    __shared__ float ins[3][128];
    __shared__ float lg[3][16];
    __shared__ float wsm[3][16];
    __shared__ float cbuf[768];

    for (int i = tid; i < Dn; i += 128) AHs[i] = g_AH[(size_t)t * Dn + i];

    float cacc[6] = {0.f, 0.f, 0.f, 0.f, 0.f, 0.f};
    float sumAcc = 0.f;

    for (int p = 0; p < Pn; p++) {
        __syncthreads();
        if (tid < 96) {
            int router = tid >> 5, n = tid & 31;
            const float* src = (router == 0) ? wQg : ((router == 1) ? wKg : wVg);
            gate[router][n] = src[((size_t)p * TOK + t) * 32 + n];
        }
        __syncthreads();
        if (tid < 48) {
            int router = tid >> 4, r = tid & 15;
            int base = (router == 2) ? 512 : 0;
            float a = 0.f;
            #pragma unroll
            for (int n = 0; n < 32; n++) a += gate[router][n] * AHs[base + n * 16 + r];
            hs[router][r] = a;
        }
        __syncthreads();
        for (int v = tid; v < 384; v += 128) {
            int router = v >> 7, i = v & 127;
            float val;
            if (i < 64) {
                const float* Wp = (router == 2) ? Wp_v : Wp_qk;
                const float* bp = (router == 2) ? bp_v : bp_qk;
                float a = bp[i];
                #pragma unroll
                for (int r = 0; r < 16; r++) a += hs[router][r] * Wp[r * 64 + i];
                val = a;
            } else {
                int d = i - 64;
                const float* emb = (router == 2) ? fv_emb : fqk_emb;
                float a = 0.f;
                #pragma unroll
                for (int n = 0; n < 32; n++) a += gate[router][n] * emb[n * 64 + d];
                val = a;
            }
            ins[router][i] = val;
        }
        __syncthreads();
        if (tid < 48) {
            int router = tid >> 4, j = tid & 15;
            const float* Wr = (router == 2) ? Wr_v : Wr_qk;
            float a = 0.f;
            for (int i = 0; i < 128; i++) a += ins[router][i] * Wr[i * 16 + j];
            lg[router][j] = a;
        }
        __syncthreads();
        if (tid < 3) {
            float mx = -1e30f;
            for (int j = 0; j < 16; j++) mx = fmaxf(mx, lg[tid][j]);
            float e[16], s = 0.f;
            for (int j = 0; j < 16; j++) { e[j] = __expf(lg[tid][j] - mx); s += e[j]; }
            float inv = 1.f / s;
            for (int j = 0; j < 16; j++) wsm[tid][j] = e[j] * inv;
        }
        __syncthreads();
        if (tid < 48) sumAcc += wsm[tid >> 4][tid & 15];
        #pragma unroll
        for (int it = 0; it < 6; it++) {
            int v = tid + it * 128;
            int router = v >> 8, idx = v & 255;
            cacc[it] += wsm[router][idx >> 4] * hs[router][idx & 15];
        }
    }
    #pragma unroll
    for (int it = 0; it < 6; it++) cbuf[tid + it * 128] = cacc[it];
    __syncthreads();
    for (int j = tid; j < 384; j += 128) {
        int router = j >> 7, j2 = j & 127;
        g_Cs[((size_t)router * TOK + t) * 128 + j2] =
            bfsplit2(cbuf[router * 256 + 2 * j2], cbuf[router * 256 + 2 * j2 + 1]);
    }
    if (tid < 48) atomicAdd(&g_rsum[tid], sumAcc);
}

// ---------------- 3xbf16 flash attention, 3-stage cp.async pipeline ----------------
// grid (S/128, B*H), 256 threads (8 warps), warp = 16 q rows, KV tile = 32.
#define KS2 36   /* K row stride in uint2 */
#define VS2 68   /* V row stride in uint2 */
#define FLASH_SMEM ((3*32*KS2 + 3*16*VS2) * 8)
__global__ __launch_bounds__(256) void k_flashmma() {
    extern __shared__ uint2 fsm[];
    uint2* Ks = fsm;                   // [3][32][KS2]
    uint2* Vs = fsm + 3 * 32 * KS2;    // [3][16][VS2]

    const int qt = blockIdx.x;
    const int bh = blockIdx.y;
    const int b = bh >> 4, h = bh & 15;
    const int tid = threadIdx.x;
    const int lane = tid & 31;
    const int warp = tid >> 5;
    const int g = lane >> 2, t = lane & 3;
    const int q0 = qt * 128 + warp * 16;

    uint32_t qh[4][4], ql[4][4];
    {
        const uint2* Qr0 = g_Qpk + (size_t)(b * Sn + q0 + g) * 512 + h * 32;
        const uint2* Qr1 = g_Qpk + (size_t)(b * Sn + q0 + g + 8) * 512 + h * 32;
        #pragma unroll
        for (int kc = 0; kc < 4; kc++) {
            uint2 a0 = Qr0[kc * 8 + t];
            uint2 a1 = Qr1[kc * 8 + t];
            uint2 a2 = Qr0[kc * 8 + t + 4];
            uint2 a3 = Qr1[kc * 8 + t + 4];
            qh[kc][0] = a0.x; qh[kc][1] = a1.x; qh[kc][2] = a2.x; qh[kc][3] = a3.x;
            ql[kc][0] = a0.y; ql[kc][1] = a1.y; ql[kc][2] = a2.y; ql[kc][3] = a3.y;
        }
    }

    float o[8][4];
    #pragma unroll
    for (int ni = 0; ni < 8; ni++)
        #pragma unroll
        for (int j = 0; j < 4; j++) o[ni][j] = 0.f;
    float m0 = -1e30f, m1 = -1e30f, l0 = 0.f, l1 = 0.f;

    const int nkt = 4 * qt + 4;

    auto loadKV = [&](int st, int kt) {
        #pragma unroll
        for (int i = 0; i < 4; i++) {
            int chunk = tid + i * 256;
            if (chunk < 512) {
                int r = chunk >> 4, cc = (chunk & 15) * 2;
                cpa16(&Ks[(st * 32 + r) * KS2 + cc],
                      g_Kpk + (size_t)(b * Sn + kt * 32 + r) * 512 + h * 32 + cc);
            } else {
                int c2 = chunk - 512;
                int r = c2 >> 5, cc = (c2 & 31) * 2;
                cpa16(&Vs[(st * 16 + r) * VS2 + cc],
                      g_Vpk + (size_t)(b * (Sn / 2) + kt * 16 + r) * 1024 + h * 64 + cc);
            }
        }
    };

    loadKV(0, 0); cpcommit();
    loadKV(1, 1); cpcommit();

    for (int kt = 0; kt < nkt; kt++) {
        if (kt + 1 < nkt) cpwaitN<1>(); else cpwaitN<0>();
        __syncthreads();
        if (kt + 2 < nkt) { loadKV((kt + 2) % 3, kt + 2); cpcommit(); }

        if (kt * 32 > q0 + 15) continue;   // fully masked for this warp
        const int st = kt % 3;

        float s[4][4];
        #pragma unroll
        for (int ni = 0; ni < 4; ni++)
            #pragma unroll
            for (int j = 0; j < 4; j++) s[ni][j] = 0.f;
        #pragma unroll
        for (int kc = 0; kc < 4; kc++) {
            #pragma unroll
            for (int ni = 0; ni < 4; ni++) {
                uint2 b0 = Ks[(st * 32 + ni * 8 + g) * KS2 + kc * 8 + t];
                uint2 b1 = Ks[(st * 32 + ni * 8 + g) * KS2 + kc * 8 + t + 4];
                mma_bf16(s[ni], qh[kc], b0.x, b1.x);
                mma_bf16(s[ni], ql[kc], b0.x, b1.x);
                mma_bf16(s[ni], qh[kc], b0.y, b1.y);
            }
        }
        #pragma unroll
        for (int ni = 0; ni < 4; ni++)
            #pragma unroll
            for (int j = 0; j < 4; j++) s[ni][j] *= 0.125f;

        if (kt * 32 + 31 > q0) {
            const int r0 = q0 + g, r1 = r0 + 8, cb = kt * 32;
            #pragma unroll
            for (int ni = 0; ni < 4; ni++) {
                int c0 = cb + ni * 8 + 2 * t;
                if (c0 > r0)     s[ni][0] = -1e30f;
                if (c0 + 1 > r0) s[ni][1] = -1e30f;
                if (c0 > r1)     s[ni][2] = -1e30f;
                if (c0 + 1 > r1) s[ni][3] = -1e30f;
            }
        }

        float mx0 = -1e30f, mx1 = -1e30f;
        #pragma unroll
        for (int ni = 0; ni < 4; ni++) {
            mx0 = fmaxf(mx0, fmaxf(s[ni][0], s[ni][1]));
            mx1 = fmaxf(mx1, fmaxf(s[ni][2], s[ni][3]));
        }
        mx0 = fmaxf(mx0, __shfl_xor_sync(0xffffffffu, mx0, 1));
        mx0 = fmaxf(mx0, __shfl_xor_sync(0xffffffffu, mx0, 2));
        mx1 = fmaxf(mx1, __shfl_xor_sync(0xffffffffu, mx1, 1));
        mx1 = fmaxf(mx1, __shfl_xor_sync(0xffffffffu, mx1, 2));
        float mn0 = fmaxf(m0, mx0), mn1 = fmaxf(m1, mx1);
        float cr0 = __expf(m0 - mn0), cr1 = __expf(m1 - mn1);
        m0 = mn0; m1 = mn1;
        #pragma unroll
        for (int ni = 0; ni < 8; ni++) {
            o[ni][0] *= cr0; o[ni][1] *= cr0;
            o[ni][2] *= cr1; o[ni][3] *= cr1;
        }

        float rs0 = 0.f, rs1 = 0.f;
        #pragma unroll
        for (int ni = 0; ni < 4; ni++) {
            s[ni][0] = __expf(s[ni][0] - m0);
            s[ni][1] = __expf(s[ni][1] - m0);
            s[ni][2] = __expf(s[ni][2] - m1);
            s[ni][3] = __expf(s[ni][3] - m1);
            rs0 += s[ni][0] + s[ni][1];
            rs1 += s[ni][2] + s[ni][3];
        }
        rs0 += __shfl_xor_sync(0xffffffffu, rs0, 1);
        rs0 += __shfl_xor_sync(0xffffffffu, rs0, 2);
        rs1 += __shfl_xor_sync(0xffffffffu, rs1, 1);
        rs1 += __shfl_xor_sync(0xffffffffu, rs1, 2);
        l0 = l0 * cr0 + rs0;
        l1 = l1 * cr1 + rs1;

        // P@V: C-fragment == A-fragment layout for bf16 — no shuffles
        #pragma unroll
        for (int kc = 0; kc < 2; kc++) {
            uint32_t pH[4], pL[4];
            uint2 f0 = bfsplit2(s[2 * kc][0], s[2 * kc][1]);
            uint2 f1 = bfsplit2(s[2 * kc][2], s[2 * kc][3]);
            uint2 f2 = bfsplit2(s[2 * kc + 1][0], s[2 * kc + 1][1]);
            uint2 f3 = bfsplit2(s[2 * kc + 1][2], s[2 * kc + 1][3]);
            pH[0] = f0.x; pH[1] = f1.x; pH[2] = f2.x; pH[3] = f3.x;
            pL[0] = f0.y; pL[1] = f1.y; pL[2] = f2.y; pL[3] = f3.y;
            #pragma unroll
            for (int ni = 0; ni < 8; ni++) {
                uint2 b0 = Vs[(st * 16 + kc * 8 + t) * VS2 + ni * 8 + g];
                uint2 b1 = Vs[(st * 16 + kc * 8 + t + 4) * VS2 + ni * 8 + g];
                mma_bf16(o[ni], pH, b0.x, b1.x);
                mma_bf16(o[ni], pL, b0.x, b1.x);
                mma_bf16(o[ni], pH, b0.y, b1.y);
            }
        }
    }

    // epilogue: normalize, q-norm scale (from g_qsq), write packed AO
    const int r0 = q0 + g, r1 = r0 + 8;
    const int tb = b * Sn;
    float qsq0 = g_qsq[tb + r0], qsq1 = g_qsq[tb + r1];
    float sc0 = (qsq0 > 1e-12f) ? 1.f : sqrtf(qsq0) * 1e-6f;
    float sc1 = (qsq1 > 1e-12f) ? 1.f : sqrtf(qsq1) * 1e-6f;
    float f0 = sc0 / l0;
    float f1 = sc1 / l1;
    #pragma unroll
    for (int ni = 0; ni < 8; ni++) {
        int cp = h * 32 + ni * 4 + t;
        g_AOs[(size_t)(tb + r0) * 512 + cp] = bfsplit2(o[ni][0] * f0, o[ni][1] * f0);
        g_AOs[(size_t)(tb + r1) * 512 + cp] = bfsplit2(o[ni][2] * f1, o[ni][3] * f1);
    }
}

// ---------------- aux loss ----------------
__global__ void k_aux(float* __restrict__ out) {
    float aux = 0.f;
    for (int router = 0; router < 3; router++) {
        float s = 0.f;
        for (int j = 0; j < 16; j++) {
            float mp = g_rsum[router * 16 + j] / (float)(Pn * TOK);
            s += mp * mp;
        }
        aux += 16.f * s;
    }
    out[(size_t)TOK * Dn] = aux;
}

// ---------------- launch ----------------
// Launch order keeps k_mma<0> at profiled slot (index 3); k_split<2> (W_O)
// deferred to slot 8 — its only consumer is k_mma<3> at slot 9.
extern "C" void kernel_launch(void* const* d_in, const int* in_sizes, int n_in,
                              void* d_out, int out_size) {
    const float* x       = (const float*)d_in[0];
    const float* wQ      = (const float*)d_in[1];
    const float* wK      = (const float*)d_in[2];
    const float* wV      = (const float*)d_in[3];
    const float* fneu    = (const float*)d_in[4];
    const float* rneu    = (const float*)d_in[5];
    const float* fqk_emb = (const float*)d_in[6];
    const float* fv_emb  = (const float*)d_in[7];
    const float* Wp_qk   = (const float*)d_in[8];
    const float* bp_qk   = (const float*)d_in[9];
    const float* Wp_v    = (const float*)d_in[10];
    const float* bp_v    = (const float*)d_in[11];
    const float* Wr_qk   = (const float*)d_in[12];
    const float* Wr_v    = (const float*)d_in[13];
    const float* W_O     = (const float*)d_in[14];
    float* out = (float*)d_out;

    // unconditional, idempotent
    cudaFuncSetAttribute(k_mma<0>,  cudaFuncAttributeMaxDynamicSharedMemorySize, GEMM_SMEM);
    cudaFuncSetAttribute(k_mma<12>, cudaFuncAttributeMaxDynamicSharedMemorySize, GEMM_SMEM);
    cudaFuncSetAttribute(k_mma<3>,  cudaFuncAttributeMaxDynamicSharedMemorySize, GEMM_SMEM);
    cudaFuncSetAttribute(k_flashmma, cudaFuncAttributeMaxDynamicSharedMemorySize, FLASH_SMEM);

    k_prep<<<2048, 256>>>(fneu);                               // 0
    k_split<0><<<(TOK * 512) / 256, 256>>>(x, TOK * 512);      // 1
    k_split<1><<<(256 * 1024) / 256, 256>>>(rneu, 256 * 1024); // 2
    k_mma<0><<<dim3(8, 64), 256, GEMM_SMEM>>>(nullptr);        // 3  <-- profiled
    k_router<<<TOK, 128>>>(wQ, wK, wV, fqk_emb, fv_emb, Wp_qk, bp_qk, Wp_v, bp_v, Wr_qk, Wr_v); // 4
    k_mma<12><<<dim3(8, 192), 256, GEMM_SMEM>>>(nullptr);      // 5
    k_packV<<<(2048 * 1024) / 256, 256>>>();                   // 6
    k_flashmma<<<dim3(Sn / 128, Bn * 16), 256, FLASH_SMEM>>>();// 7
    k_split<2><<<(512 * 1024) / 256, 256>>>(W_O, 512 * 1024);  // 8
    k_mma<3><<<dim3(8, 64), 256, GEMM_SMEM>>>(out);            // 9
    if (out_size > TOK * Dn) k_aux<<<1, 1>>>(out);             // 10
}

// round 17
// speedup vs baseline: 1.0558x; 1.0237x over previous
#include <cuda_runtime.h>
#include <cuda_bf16.h>
#include <math.h>
#include <stdint.h>

// ---------------- problem constants ----------------
#define Pn 2
#define Bn 2
#define Sn 2048
#define Dn 1024
#define TOK 4096

// ---------------- scratch: packed bf16x2 split planes (uint2 = {hi-pair, lo-pair}) ----------------
__device__ __align__(16) uint2 g_Xs[(size_t)TOK*512];       // x, d-pair packed
__device__ __align__(16) uint2 g_Falls[(size_t)512*1024];   // f_neurons^T, d(k)-pair packed
__device__ __align__(16) uint2 g_Rs[(size_t)256*1024];      // r_neurons (qk|v), k-pair packed
__device__ __align__(16) uint2 g_WOs[(size_t)512*1024];     // W_O, k-pair packed
__device__ __align__(16) uint2 g_Cs[(size_t)3*TOK*128];     // CQ|CK|CV, k-pair packed
__device__ __align__(16) uint2 g_Qpk[(size_t)TOK*512];      // Q, d-pair packed
__device__ __align__(16) uint2 g_Kpk[(size_t)TOK*512];      // K, d-pair packed
__device__ __align__(16) uint2 g_Vpk[(size_t)(TOK/2)*1024]; // V, key-pair packed
__device__ __align__(16) uint2 g_AOs[(size_t)TOK*512];      // attn out, d-pair packed
__device__ __align__(16) float g_AH[(size_t)TOK*Dn];        // all_h (router input)
__device__ __align__(16) float g_Vf[(size_t)TOK*Dn];        // V float (pack input)
__device__ float g_qsq[TOK];                                // |Q|^2 partials
__device__ float g_rsum[48];

// ---------------- helpers ----------------
__device__ __forceinline__ uint32_t bf16bits(float x) {
    __nv_bfloat16 h = __float2bfloat16_rn(x);
    return (uint32_t)*reinterpret_cast<uint16_t*>(&h);
}
__device__ __forceinline__ float bf16val(uint32_t b) {
    uint16_t u = (uint16_t)b;
    __nv_bfloat16 h = *reinterpret_cast<__nv_bfloat16*>(&u);
    return __bfloat162float(h);
}
__device__ __forceinline__ uint2 bfsplit2(float a, float b) {
    uint32_t ha = bf16bits(a), hb = bf16bits(b);
    uint32_t la = bf16bits(a - bf16val(ha));
    uint32_t lb = bf16bits(b - bf16val(hb));
    return make_uint2(ha | (hb << 16), la | (lb << 16));
}
__device__ __forceinline__ void mma_bf16(float* d, const uint32_t* a, uint32_t b0, uint32_t b1) {
    asm volatile("mma.sync.aligned.m16n8k16.row.col.f32.bf16.bf16.f32 "
                 "{%0,%1,%2,%3},{%4,%5,%6,%7},{%8,%9},{%0,%1,%2,%3};"
                 : "+f"(d[0]), "+f"(d[1]), "+f"(d[2]), "+f"(d[3])
                 : "r"(a[0]), "r"(a[1]), "r"(a[2]), "r"(a[3]), "r"(b0), "r"(b1));
}
__device__ __forceinline__ void cpa16(void* smem, const void* gmem) {
    uint32_t s = (uint32_t)__cvta_generic_to_shared(smem);
    asm volatile("cp.async.cg.shared.global [%0], [%1], 16;" :: "r"(s), "l"(gmem) : "memory");
}
__device__ __forceinline__ void cpcommit() { asm volatile("cp.async.commit_group;" ::: "memory"); }
template<int N>
__device__ __forceinline__ void cpwaitN() { asm volatile("cp.async.wait_group %0;" :: "n"(N) : "memory"); }

// ---------------- prep: transpose+split f_neurons, zero accumulators ----------------
__global__ void k_prep(const float* __restrict__ fneu) {
    int idx = blockIdx.x * blockDim.x + threadIdx.x;
    if (blockIdx.x == 0 && threadIdx.x < 48) g_rsum[threadIdx.x] = 0.f;
    if (idx < TOK) g_qsq[idx] = 0.f;
    if (idx < 512 * 1024) {
        int d2 = idx >> 10, c = idx & 1023;
        int n = c >> 4, r = c & 15;
        float v0 = fneu[((size_t)n * 1024 + 2 * d2) * 16 + r];
        float v1 = fneu[((size_t)n * 1024 + 2 * d2 + 1) * 16 + r];
        g_Falls[idx] = bfsplit2(v0, v1);
    }
}

// ---------------- split kernels ----------------
template<int W>
__global__ void k_split(const float* __restrict__ src, int n) {
    int idx = blockIdx.x * blockDim.x + threadIdx.x;
    if (idx >= n) return;
    if (W == 0) {
        float2 v = *reinterpret_cast<const float2*>(src + (size_t)2 * idx);
        g_Xs[idx] = bfsplit2(v.x, v.y);
    }
    if (W == 1) {
        int k2 = idx >> 10, c = idx & 1023;
        g_Rs[idx] = bfsplit2(src[(size_t)2 * k2 * 1024 + c], src[(size_t)(2 * k2 + 1) * 1024 + c]);
    }
    if (W == 2) {
        int k2 = idx >> 10, c = idx & 1023;
        g_WOs[idx] = bfsplit2(src[(size_t)2 * k2 * 1024 + c], src[(size_t)(2 * k2 + 1) * 1024 + c]);
    }
}

// pack V: key-pair packed planes (coalesced)
__global__ void k_packV() {
    int idx = blockIdx.x * blockDim.x + threadIdx.x;
    if (idx >= 2048 * 1024) return;
    int row2 = idx >> 10, d = idx & 1023;
    int b = row2 >> 10, kl = row2 & 1023;
    size_t tok = (size_t)b * 2048 + 2 * kl;
    g_Vpk[idx] = bfsplit2(g_Vf[tok * 1024 + d], g_Vf[(tok + 1) * 1024 + d]);
}

// ---------------- 3xbf16 GEMM, 4-stage cp.async pipeline, BK=32 ----------------
// block tile 64x128x32, 8 warps (2x4), warp tile 32x32, 2 k16-subchunks per stage.
// MODE 0: AH = X @ Fall.  MODE 12: QKV = C @ r (grid y=192).  MODE 3: out = AO @ W_O.
#define AS2 20    /* As row stride in uint2 (16 data + 4 pad) */
#define BS2 132   /* Bs row stride in uint2 */
#define GEMM_SMEM ((4*64*AS2 + 4*16*BS2) * 8)
template<int MODE>
__global__ __launch_bounds__(256) void k_mma(float* __restrict__ extC) {
    constexpr int K2 = (MODE == 12) ? 128 : 512;   // k-pairs per row
    constexpr int N = 1024;
    constexpr int NIT = K2 / 16;                   // BK=32 elems = 16 pairs per stage

    const uint2* A; const uint2* B;
    if (MODE == 0)  { A = g_Xs;  B = g_Falls; }
    if (MODE == 12) { A = g_Cs;  B = (blockIdx.y < 128) ? g_Rs : (g_Rs + (size_t)128 * 1024); }
    if (MODE == 3)  { A = g_AOs; B = g_WOs; }

    extern __shared__ uint2 sm[];
    uint2* As = sm;                    // [4][64][AS2]
    uint2* Bs = sm + 4 * 64 * AS2;     // [4][16][BS2]

    const int tid  = threadIdx.x;
    const int lane = tid & 31;
    const int warp = tid >> 5;
    const int wr = warp >> 2;          // 0..1
    const int wc = warp & 3;           // 0..3
    const int g = lane >> 2;
    const int t = lane & 3;
    const int bx = blockIdx.x, by = blockIdx.y;

    float acc[2][4][4];
    #pragma unroll
    for (int mi = 0; mi < 2; mi++)
        #pragma unroll
        for (int ni = 0; ni < 4; ni++)
            #pragma unroll
            for (int j = 0; j < 4; j++) acc[mi][ni][j] = 0.f;

    const uint2* Ab = A + (size_t)by * 64 * K2;
    const uint2* Bb = B + (size_t)bx * 128;

    auto loadStage = [&](int st, int k20) {
        #pragma unroll
        for (int i = 0; i < 2; i++) {  // A: 64 rows x 16 pairs = 512 chunks
            int chunk = tid + i * 256;
            int r = chunk >> 3, cc = (chunk & 7) * 2;
            cpa16(&As[(st * 64 + r) * AS2 + cc], Ab + (size_t)r * K2 + k20 + cc);
        }
        #pragma unroll
        for (int i = 0; i < 4; i++) {  // B: 16 rows x 128 cols = 1024 chunks
            int chunk = tid + i * 256;
            int kr = chunk >> 6, cc = (chunk & 63) * 2;
            cpa16(&Bs[(st * 16 + kr) * BS2 + cc], Bb + (size_t)(k20 + kr) * N + cc);
        }
    };

    loadStage(0, 0);  cpcommit();
    loadStage(1, 16); cpcommit();
    loadStage(2, 32); cpcommit();

    #pragma unroll 4
    for (int it = 0; it < NIT; it++) {
        if (it + 2 < NIT) cpwaitN<2>();
        else if (it + 1 < NIT) cpwaitN<1>();
        else cpwaitN<0>();
        __syncthreads();
        if (it + 3 < NIT) { loadStage((it + 3) & 3, (it + 3) * 16); cpcommit(); }

        const int st = it & 3;
        #pragma unroll
        for (int sub = 0; sub < 2; sub++) {
            const int ko = sub * 8;
            uint32_t ah[2][4], al[2][4];
            #pragma unroll
            for (int mi = 0; mi < 2; mi++) {
                int r0 = wr * 32 + mi * 16 + g;
                uint2 a0 = As[(st * 64 + r0) * AS2 + ko + t];
                uint2 a1 = As[(st * 64 + r0 + 8) * AS2 + ko + t];
                uint2 a2 = As[(st * 64 + r0) * AS2 + ko + t + 4];
                uint2 a3 = As[(st * 64 + r0 + 8) * AS2 + ko + t + 4];
                ah[mi][0] = a0.x; ah[mi][1] = a1.x; ah[mi][2] = a2.x; ah[mi][3] = a3.x;
                al[mi][0] = a0.y; al[mi][1] = a1.y; al[mi][2] = a2.y; al[mi][3] = a3.y;
            }
            #pragma unroll
            for (int ni = 0; ni < 4; ni++) {
                int c = wc * 32 + ni * 8 + g;
                uint2 b0 = Bs[(st * 16 + ko + t) * BS2 + c];
                uint2 b1 = Bs[(st * 16 + ko + t + 4) * BS2 + c];
                #pragma unroll
                for (int mi = 0; mi < 2; mi++) {
                    mma_bf16(acc[mi][ni], ah[mi], b0.x, b1.x);
                    mma_bf16(acc[mi][ni], al[mi], b0.x, b1.x);
                    mma_bf16(acc[mi][ni], ah[mi], b0.y, b1.y);
                }
            }
        }
    }

    // epilogue
    #pragma unroll
    for (int mi = 0; mi < 2; mi++) {
        int r0 = by * 64 + wr * 32 + mi * 16 + g;
        float qs0 = 0.f, qs1 = 0.f;
        #pragma unroll
        for (int ni = 0; ni < 4; ni++) {
            int c = bx * 128 + wc * 32 + ni * 8 + 2 * t;
            int cp = c >> 1;
            float v0 = acc[mi][ni][0], v1 = acc[mi][ni][1];
            float v2 = acc[mi][ni][2], v3 = acc[mi][ni][3];
            if (MODE == 0) {
                *reinterpret_cast<float2*>(g_AH + (size_t)r0 * N + c) = make_float2(v0, v1);
                *reinterpret_cast<float2*>(g_AH + (size_t)(r0 + 8) * N + c) = make_float2(v2, v3);
            }
            if (MODE == 3) {
                *reinterpret_cast<float2*>(extC + (size_t)r0 * N + c) = make_float2(v0, v1);
                *reinterpret_cast<float2*>(extC + (size_t)(r0 + 8) * N + c) = make_float2(v2, v3);
            }
            if (MODE == 12) {
                if (r0 < TOK) {            // Q rows
                    qs0 += v0 * v0 + v1 * v1;
                    qs1 += v2 * v2 + v3 * v3;
                    g_Qpk[(size_t)r0 * 512 + cp] = bfsplit2(v0, v1);
                    g_Qpk[(size_t)(r0 + 8) * 512 + cp] = bfsplit2(v2, v3);
                } else if (r0 < 2 * TOK) { // K rows
                    g_Kpk[(size_t)(r0 - TOK) * 512 + cp] = bfsplit2(v0, v1);
                    g_Kpk[(size_t)(r0 + 8 - TOK) * 512 + cp] = bfsplit2(v2, v3);
                } else {                   // V rows: float out, packed later (coalesced)
                    *reinterpret_cast<float2*>(g_Vf + (size_t)(r0 - 2 * TOK) * N + c) = make_float2(v0, v1);
                    *reinterpret_cast<float2*>(g_Vf + (size_t)(r0 + 8 - 2 * TOK) * N + c) = make_float2(v2, v3);
                }
            }
        }
        if (MODE == 12 && r0 < TOK) {
            atomicAdd(&g_qsq[r0], qs0);
            atomicAdd(&g_qsq[r0 + 8], qs1);
        }
    }
}

// ---------------- per-token router / coefficient kernel ----------------
__global__ __launch_bounds__(128) void k_router(
    const float* __restrict__ wQg, const float* __restrict__ wKg, const float* __restrict__ wVg,
    const float* __restrict__ fqk_emb, const float* __restrict__ fv_emb,
    const float* __restrict__ Wp_qk, const float* __restrict__ bp_qk,
    const float* __restrict__ Wp_v, const float* __restrict__ bp_v,
    const float* __restrict__ Wr_qk, const float* __restrict__ Wr_v)
{
    const int t = blockIdx.x;
    const int tid = threadIdx.x;
    __shared__ float AHs[Dn];
    __shared__ float gate[3][32];
    __shared__ float hs[3][16];
    __shared__ float ins[3][128];
    __shared__ float lg[3][16];
    __shared__ float wsm[3][16];
    __shared__ float cbuf[768];

    for (int i = tid; i < Dn; i += 128) AHs[i] = g_AH[(size_t)t * Dn + i];

    float cacc[6] = {0.f, 0.f, 0.f, 0.f, 0.f, 0.f};
    float sumAcc = 0.f;

    for (int p = 0; p < Pn; p++) {
        __syncthreads();
        if (tid < 96) {
            int router = tid >> 5, n = tid & 31;
            const float* src = (router == 0) ? wQg : ((router == 1) ? wKg : wVg);
            gate[router][n] = src[((size_t)p * TOK + t) * 32 + n];
        }
        __syncthreads();
        if (tid < 48) {
            int router = tid >> 4, r = tid & 15;
            int base = (router == 2) ? 512 : 0;
            float a = 0.f;
            #pragma unroll
            for (int n = 0; n < 32; n++) a += gate[router][n] * AHs[base + n * 16 + r];
            hs[router][r] = a;
        }
        __syncthreads();
        for (int v = tid; v < 384; v += 128) {
            int router = v >> 7, i = v & 127;
            float val;
            if (i < 64) {
                const float* Wp = (router == 2) ? Wp_v : Wp_qk;
                const float* bp = (router == 2) ? bp_v : bp_qk;
                float a = bp[i];
                #pragma unroll
                for (int r = 0; r < 16; r++) a += hs[router][r] * Wp[r * 64 + i];
                val = a;
            } else {
                int d = i - 64;
                const float* emb = (router == 2) ? fv_emb : fqk_emb;
                float a = 0.f;
                #pragma unroll
                for (int n = 0; n < 32; n++) a += gate[router][n] * emb[n * 64 + d];
                val = a;
            }
            ins[router][i] = val;
        }
        __syncthreads();
        if (tid < 48) {
            int router = tid >> 4, j = tid & 15;
            const float* Wr = (router == 2) ? Wr_v : Wr_qk;
            float a = 0.f;
            for (int i = 0; i < 128; i++) a += ins[router][i] * Wr[i * 16 + j];
            lg[router][j] = a;
        }
        __syncthreads();
        if (tid < 3) {
            float mx = -1e30f;
            for (int j = 0; j < 16; j++) mx = fmaxf(mx, lg[tid][j]);
            float e[16], s = 0.f;
            for (int j = 0; j < 16; j++) { e[j] = __expf(lg[tid][j] - mx); s += e[j]; }
            float inv = 1.f / s;
            for (int j = 0; j < 16; j++) wsm[tid][j] = e[j] * inv;
        }
        __syncthreads();
        if (tid < 48) sumAcc += wsm[tid >> 4][tid & 15];
        #pragma unroll
        for (int it = 0; it < 6; it++) {
            int v = tid + it * 128;
            int router = v >> 8, idx = v & 255;
            cacc[it] += wsm[router][idx >> 4] * hs[router][idx & 15];
        }
    }
    #pragma unroll
    for (int it = 0; it < 6; it++) cbuf[tid + it * 128] = cacc[it];
    __syncthreads();
    for (int j = tid; j < 384; j += 128) {
        int router = j >> 7, j2 = j & 127;
        g_Cs[((size_t)router * TOK + t) * 128 + j2] =
            bfsplit2(cbuf[router * 256 + 2 * j2], cbuf[router * 256 + 2 * j2 + 1]);
    }
    if (tid < 48) atomicAdd(&g_rsum[tid], sumAcc);
}

// ---------------- 3xbf16 flash attention, 3-stage cp.async pipeline ----------------
// grid (S/128, B*H), 256 threads (8 warps), warp = 16 q rows, KV tile = 32.
#define KS2 36   /* K row stride in uint2 */
#define VS2 68   /* V row stride in uint2 */
#define FLASH_SMEM ((3*32*KS2 + 3*16*VS2) * 8)
__global__ __launch_bounds__(256) void k_flashmma() {
    extern __shared__ uint2 fsm[];
    uint2* Ks = fsm;                   // [3][32][KS2]
    uint2* Vs = fsm + 3 * 32 * KS2;    // [3][16][VS2]

    const int qt = blockIdx.x;
    const int bh = blockIdx.y;
    const int b = bh >> 4, h = bh & 15;
    const int tid = threadIdx.x;
    const int lane = tid & 31;
    const int warp = tid >> 5;
    const int g = lane >> 2, t = lane & 3;
    const int q0 = qt * 128 + warp * 16;

    uint32_t qh[4][4], ql[4][4];
    {
        const uint2* Qr0 = g_Qpk + (size_t)(b * Sn + q0 + g) * 512 + h * 32;
        const uint2* Qr1 = g_Qpk + (size_t)(b * Sn + q0 + g + 8) * 512 + h * 32;
        #pragma unroll
        for (int kc = 0; kc < 4; kc++) {
            uint2 a0 = Qr0[kc * 8 + t];
            uint2 a1 = Qr1[kc * 8 + t];
            uint2 a2 = Qr0[kc * 8 + t + 4];
            uint2 a3 = Qr1[kc * 8 + t + 4];
            qh[kc][0] = a0.x; qh[kc][1] = a1.x; qh[kc][2] = a2.x; qh[kc][3] = a3.x;
            ql[kc][0] = a0.y; ql[kc][1] = a1.y; ql[kc][2] = a2.y; ql[kc][3] = a3.y;
        }
    }

    float o[8][4];
    #pragma unroll
    for (int ni = 0; ni < 8; ni++)
        #pragma unroll
        for (int j = 0; j < 4; j++) o[ni][j] = 0.f;
    float m0 = -1e30f, m1 = -1e30f, l0 = 0.f, l1 = 0.f;

    const int nkt = 4 * qt + 4;

    auto loadKV = [&](int st, int kt) {
        #pragma unroll
        for (int i = 0; i < 4; i++) {
            int chunk = tid + i * 256;
            if (chunk < 512) {
                int r = chunk >> 4, cc = (chunk & 15) * 2;
                cpa16(&Ks[(st * 32 + r) * KS2 + cc],
                      g_Kpk + (size_t)(b * Sn + kt * 32 + r) * 512 + h * 32 + cc);
            } else {
                int c2 = chunk - 512;
                int r = c2 >> 5, cc = (c2 & 31) * 2;
                cpa16(&Vs[(st * 16 + r) * VS2 + cc],
                      g_Vpk + (size_t)(b * (Sn / 2) + kt * 16 + r) * 1024 + h * 64 + cc);
            }
        }
    };

    loadKV(0, 0); cpcommit();
    loadKV(1, 1); cpcommit();

    for (int kt = 0; kt < nkt; kt++) {
        if (kt + 1 < nkt) cpwaitN<1>(); else cpwaitN<0>();
        __syncthreads();
        if (kt + 2 < nkt) { loadKV((kt + 2) % 3, kt + 2); cpcommit(); }

        if (kt * 32 > q0 + 15) continue;   // fully masked for this warp
        const int st = kt % 3;

        float s[4][4];
        #pragma unroll
        for (int ni = 0; ni < 4; ni++)
            #pragma unroll
            for (int j = 0; j < 4; j++) s[ni][j] = 0.f;
        #pragma unroll
        for (int kc = 0; kc < 4; kc++) {
            #pragma unroll
            for (int ni = 0; ni < 4; ni++) {
                uint2 b0 = Ks[(st * 32 + ni * 8 + g) * KS2 + kc * 8 + t];
                uint2 b1 = Ks[(st * 32 + ni * 8 + g) * KS2 + kc * 8 + t + 4];
                mma_bf16(s[ni], qh[kc], b0.x, b1.x);
                mma_bf16(s[ni], ql[kc], b0.x, b1.x);
                mma_bf16(s[ni], qh[kc], b0.y, b1.y);
            }
        }
        #pragma unroll
        for (int ni = 0; ni < 4; ni++)
            #pragma unroll
            for (int j = 0; j < 4; j++) s[ni][j] *= 0.125f;

        if (kt * 32 + 31 > q0) {
            const int r0 = q0 + g, r1 = r0 + 8, cb = kt * 32;
            #pragma unroll
            for (int ni = 0; ni < 4; ni++) {
                int c0 = cb + ni * 8 + 2 * t;
                if (c0 > r0)     s[ni][0] = -1e30f;
                if (c0 + 1 > r0) s[ni][1] = -1e30f;
                if (c0 > r1)     s[ni][2] = -1e30f;
                if (c0 + 1 > r1) s[ni][3] = -1e30f;
            }
        }

        float mx0 = -1e30f, mx1 = -1e30f;
        #pragma unroll
        for (int ni = 0; ni < 4; ni++) {
            mx0 = fmaxf(mx0, fmaxf(s[ni][0], s[ni][1]));
            mx1 = fmaxf(mx1, fmaxf(s[ni][2], s[ni][3]));
        }
        mx0 = fmaxf(mx0, __shfl_xor_sync(0xffffffffu, mx0, 1));
        mx0 = fmaxf(mx0, __shfl_xor_sync(0xffffffffu, mx0, 2));
        mx1 = fmaxf(mx1, __shfl_xor_sync(0xffffffffu, mx1, 1));
        mx1 = fmaxf(mx1, __shfl_xor_sync(0xffffffffu, mx1, 2));
        float mn0 = fmaxf(m0, mx0), mn1 = fmaxf(m1, mx1);
        float cr0 = __expf(m0 - mn0), cr1 = __expf(m1 - mn1);
        m0 = mn0; m1 = mn1;
        #pragma unroll
        for (int ni = 0; ni < 8; ni++) {
            o[ni][0] *= cr0; o[ni][1] *= cr0;
            o[ni][2] *= cr1; o[ni][3] *= cr1;
        }

        float rs0 = 0.f, rs1 = 0.f;
        #pragma unroll
        for (int ni = 0; ni < 4; ni++) {
            s[ni][0] = __expf(s[ni][0] - m0);
            s[ni][1] = __expf(s[ni][1] - m0);
            s[ni][2] = __expf(s[ni][2] - m1);
            s[ni][3] = __expf(s[ni][3] - m1);
            rs0 += s[ni][0] + s[ni][1];
            rs1 += s[ni][2] + s[ni][3];
        }
        rs0 += __shfl_xor_sync(0xffffffffu, rs0, 1);
        rs0 += __shfl_xor_sync(0xffffffffu, rs0, 2);
        rs1 += __shfl_xor_sync(0xffffffffu, rs1, 1);
        rs1 += __shfl_xor_sync(0xffffffffu, rs1, 2);
        l0 = l0 * cr0 + rs0;
        l1 = l1 * cr1 + rs1;

        // P@V: C-fragment == A-fragment layout for bf16 — no shuffles
        #pragma unroll
        for (int kc = 0; kc < 2; kc++) {
            uint32_t pH[4], pL[4];
            uint2 f0 = bfsplit2(s[2 * kc][0], s[2 * kc][1]);
            uint2 f1 = bfsplit2(s[2 * kc][2], s[2 * kc][3]);
            uint2 f2 = bfsplit2(s[2 * kc + 1][0], s[2 * kc + 1][1]);
            uint2 f3 = bfsplit2(s[2 * kc + 1][2], s[2 * kc + 1][3]);
            pH[0] = f0.x; pH[1] = f1.x; pH[2] = f2.x; pH[3] = f3.x;
            pL[0] = f0.y; pL[1] = f1.y; pL[2] = f2.y; pL[3] = f3.y;
            #pragma unroll
            for (int ni = 0; ni < 8; ni++) {
                uint2 b0 = Vs[(st * 16 + kc * 8 + t) * VS2 + ni * 8 + g];
                uint2 b1 = Vs[(st * 16 + kc * 8 + t + 4) * VS2 + ni * 8 + g];
                mma_bf16(o[ni], pH, b0.x, b1.x);
                mma_bf16(o[ni], pL, b0.x, b1.x);
                mma_bf16(o[ni], pH, b0.y, b1.y);
            }
        }
    }

    // epilogue: normalize, q-norm scale (from g_qsq), write packed AO
    const int r0 = q0 + g, r1 = r0 + 8;
    const int tb = b * Sn;
    float qsq0 = g_qsq[tb + r0], qsq1 = g_qsq[tb + r1];
    float sc0 = (qsq0 > 1e-12f) ? 1.f : sqrtf(qsq0) * 1e-6f;
    float sc1 = (qsq1 > 1e-12f) ? 1.f : sqrtf(qsq1) * 1e-6f;
    float f0 = sc0 / l0;
    float f1 = sc1 / l1;
    #pragma unroll
    for (int ni = 0; ni < 8; ni++) {
        int cp = h * 32 + ni * 4 + t;
        g_AOs[(size_t)(tb + r0) * 512 + cp] = bfsplit2(o[ni][0] * f0, o[ni][1] * f0);
        g_AOs[(size_t)(tb + r1) * 512 + cp] = bfsplit2(o[ni][2] * f1, o[ni][3] * f1);
    }
}

// ---------------- aux loss ----------------
__global__ void k_aux(float* __restrict__ out) {
    float aux = 0.f;
    for (int router = 0; router < 3; router++) {
        float s = 0.f;
        for (int j = 0; j < 16; j++) {
            float mp = g_rsum[router * 16 + j] / (float)(Pn * TOK);
            s += mp * mp;
        }
        aux += 16.f * s;
    }
    out[(size_t)TOK * Dn] = aux;
}

// ---------------- launch ----------------
// Launch order keeps k_mma<0> at profiled slot (index 3); k_split<2> (W_O)
// deferred to slot 8 — its only consumer is k_mma<3> at slot 9.
extern "C" void kernel_launch(void* const* d_in, const int* in_sizes, int n_in,
                              void* d_out, int out_size) {
    const float* x       = (const float*)d_in[0];
    const float* wQ      = (const float*)d_in[1];
    const float* wK      = (const float*)d_in[2];
    const float* wV      = (const float*)d_in[3];
    const float* fneu    = (const float*)d_in[4];
    const float* rneu    = (const float*)d_in[5];
    const float* fqk_emb = (const float*)d_in[6];
    const float* fv_emb  = (const float*)d_in[7];
    const float* Wp_qk   = (const float*)d_in[8];
    const float* bp_qk   = (const float*)d_in[9];
    const float* Wp_v    = (const float*)d_in[10];
    const float* bp_v    = (const float*)d_in[11];
    const float* Wr_qk   = (const float*)d_in[12];
    const float* Wr_v    = (const float*)d_in[13];
    const float* W_O     = (const float*)d_in[14];
    float* out = (float*)d_out;

    // unconditional, idempotent
    cudaFuncSetAttribute(k_mma<0>,  cudaFuncAttributeMaxDynamicSharedMemorySize, GEMM_SMEM);
    cudaFuncSetAttribute(k_mma<12>, cudaFuncAttributeMaxDynamicSharedMemorySize, GEMM_SMEM);
    cudaFuncSetAttribute(k_mma<3>,  cudaFuncAttributeMaxDynamicSharedMemorySize, GEMM_SMEM);
    cudaFuncSetAttribute(k_flashmma, cudaFuncAttributeMaxDynamicSharedMemorySize, FLASH_SMEM);

    k_prep<<<2048, 256>>>(fneu);                               // 0
    k_split<0><<<(TOK * 512) / 256, 256>>>(x, TOK * 512);      // 1
    k_split<1><<<(256 * 1024) / 256, 256>>>(rneu, 256 * 1024); // 2
    k_mma<0><<<dim3(8, 64), 256, GEMM_SMEM>>>(nullptr);        // 3  <-- profiled
    k_router<<<TOK, 128>>>(wQ, wK, wV, fqk_emb, fv_emb, Wp_qk, bp_qk, Wp_v, bp_v, Wr_qk, Wr_v); // 4
    k_mma<12><<<dim3(8, 192), 256, GEMM_SMEM>>>(nullptr);      // 5
    k_packV<<<(2048 * 1024) / 256, 256>>>();                   // 6
    k_flashmma<<<dim3(Sn / 128, Bn * 16), 256, FLASH_SMEM>>>();// 7
    k_split<2><<<(512 * 1024) / 256, 256>>>(W_O, 512 * 1024);  // 8
    k_mma<3><<<dim3(8, 64), 256, GEMM_SMEM>>>(out);            // 9
    if (out_size > TOK * Dn) k_aux<<<1, 1>>>(out);             // 10
}